// round 12
// baseline (speedup 1.0000x reference)
#include <cuda_runtime.h>
#include <cstdint>

// Problem constants
#define CB 2
#define CN 512
#define CA 14
#define CDIM 1024
#define CH 16
#define CD 64
#define CT (CB * CN * CA)        // 14336 tokens
#define CQKVN (3 * CDIM)         // 3072

// Scratch (device globals: allowed; no runtime allocation)
// xr, bt1, bt2, g_att use a k-permuted layout: within every 8-wide group
// along K, logical column c sits at physical 2*(c&3)+(c>>2) -> LDS.64 pairs.
__device__ float g_qkv[(size_t)CT * CQKVN];    // [T, 3072] (normal layout)
__device__ float g_att[(size_t)CT * CDIM];     // [T, 1024] k-permuted, tf32
__device__ float g_xr [(size_t)CT * CDIM];     // x, k-permuted, tf32
__device__ float g_bt1[(size_t)CQKVN * CDIM];  // w_qkv^T, k-permuted, tf32
__device__ float g_bt2[(size_t)CDIM * CDIM];   // w_proj^T, k-permuted, tf32

__device__ __forceinline__ float tf32r(float x) {
    uint32_t u;
    asm("cvt.rna.tf32.f32 %0, %1;" : "=r"(u) : "f"(x));
    return __uint_as_float(u);
}

__device__ __forceinline__ uint32_t smem_u32(const void* p) {
    uint32_t a;
    asm("{ .reg .u64 t; cvta.to.shared.u64 t, %1; cvt.u32.u64 %0, t; }"
        : "=r"(a) : "l"(p));
    return a;
}

__device__ __forceinline__ void cp_async16(uint32_t smem_addr, const void* gptr) {
    asm volatile("cp.async.ca.shared.global [%0], [%1], 16;"
                 :: "r"(smem_addr), "l"(gptr) : "memory");
}
__device__ __forceinline__ void cp_commit() {
    asm volatile("cp.async.commit_group;" ::: "memory");
}
__device__ __forceinline__ void cp_wait0() {
    asm volatile("cp.async.wait_group 0;" ::: "memory");
}

__device__ __forceinline__ void mma_tf32(
    float& c0, float& c1, float& c2, float& c3,
    uint32_t a0, uint32_t a1, uint32_t a2, uint32_t a3,
    uint32_t b0, uint32_t b1)
{
    asm volatile(
        "mma.sync.aligned.m16n8k8.row.col.f32.tf32.tf32.f32 "
        "{%0,%1,%2,%3}, {%4,%5,%6,%7}, {%8,%9}, {%0,%1,%2,%3};"
        : "+f"(c0), "+f"(c1), "+f"(c2), "+f"(c3)
        : "r"(a0), "r"(a1), "r"(a2), "r"(a3), "r"(b0), "r"(b1));
}

// ===========================================================================
// Pre-pass kernels (k-permuted outputs) — unchanged from R11
// ===========================================================================
__global__ void round_perm_kernel(const float* __restrict__ in,
                                  float* __restrict__ out, int n8)
{
    int i = blockIdx.x * blockDim.x + threadIdx.x;
    if (i < n8) {
        float4 lo = ((const float4*)in)[i * 2];
        float4 hi = ((const float4*)in)[i * 2 + 1];
        float4 p0, p1;
        p0.x = tf32r(lo.x); p0.y = tf32r(hi.x);
        p0.z = tf32r(lo.y); p0.w = tf32r(hi.y);
        p1.x = tf32r(lo.z); p1.y = tf32r(hi.z);
        p1.z = tf32r(lo.w); p1.w = tf32r(hi.w);
        ((float4*)out)[i * 2]     = p0;
        ((float4*)out)[i * 2 + 1] = p1;
    }
}

__global__ void transpose_round_perm_kernel(const float* __restrict__ in,
                                            float* __restrict__ out, int K, int N)
{
    __shared__ float t[32][33];
    int n0 = blockIdx.x * 32, k0 = blockIdx.y * 32;
    int tx = threadIdx.x;
    for (int j = threadIdx.y; j < 32; j += 8)
        t[j][tx] = in[(size_t)(k0 + j) * N + n0 + tx];
    __syncthreads();
    int px = (tx & ~7) | (2 * (tx & 3) + ((tx & 7) >> 2));
    for (int j = threadIdx.y; j < 32; j += 8)
        out[(size_t)(n0 + j) * K + k0 + px] = tf32r(t[tx][j]);
}

// ===========================================================================
// tf32 mma.sync GEMM: C[M,N] = A[M,K] @ Bt[N,K]^T + bias
// 128x256 CTA tile, BK=32, 8 warps (2x4), warp tile 64x64 (mt=4, nt=8).
// 1 CTA/SM, 255-reg budget (acc=128). 2-stage cp.async, k-permuted operands,
// single __syncthreads per K-iteration (bottom sync proven redundant:
// stage written at kt is (kt+1)&1, stage read is kt&1 — disjoint).
// ===========================================================================
#define GPAD 40
#define GA_TILE (128 * GPAD)           // floats per A stage
#define GB_TILE (256 * GPAD)           // floats per B stage
#define GM_SMEM_BYTES ((2 * GA_TILE + 2 * GB_TILE) * 4)   // 122880

__global__ void __launch_bounds__(256, 1) gemm_tf32mma(
    const float* __restrict__ A, const float* __restrict__ Bt,
    const float* __restrict__ bias, float* __restrict__ C,
    int N, int K)
{
    extern __shared__ float sm[];
    float* sA = sm;                    // [2][128][GPAD]
    float* sB = sm + 2 * GA_TILE;      // [2][256][GPAD]

    const int tid  = threadIdx.x;
    const int wid  = tid >> 5;
    const int lane = tid & 31;
    const int wm   = wid >> 2;          // 0..1 (64 rows each)
    const int wn   = wid & 3;           // 0..3 (64 cols each)
    const int r0   = lane >> 2;
    const int cc   = lane & 3;

    const int mBase = blockIdx.y * 128;
    const int nBase = blockIdx.x * 256;

    const int lrow = tid >> 3;          // 0..31
    const int lcol = (tid & 7) << 2;    // 0..28

    const float* Ag = A  + (size_t)(mBase + lrow) * K + lcol;
    const float* Bg = Bt + (size_t)(nBase + lrow) * K + lcol;
    const uint32_t sAu = smem_u32(sA);
    const uint32_t sBu = smem_u32(sB);

    const int KIT = K >> 5;

    // prologue: stage 0
    {
#pragma unroll
        for (int p = 0; p < 4; p++) {
            int row = lrow + p * 32;
            cp_async16(sAu + (row * GPAD + lcol) * 4, Ag + (size_t)p * 32 * K);
        }
#pragma unroll
        for (int p = 0; p < 8; p++) {
            int row = lrow + p * 32;
            cp_async16(sBu + (row * GPAD + lcol) * 4, Bg + (size_t)p * 32 * K);
        }
        cp_commit();
    }

    float acc[4][8][4];
#pragma unroll
    for (int mt = 0; mt < 4; mt++)
#pragma unroll
        for (int nt = 0; nt < 8; nt++)
#pragma unroll
            for (int q = 0; q < 4; q++) acc[mt][nt][q] = 0.f;

    for (int kt = 0; kt < KIT; kt++) {
        cp_wait0();
        __syncthreads();

        const int s = kt & 1;
        if (kt + 1 < KIT) {
            const int ns = (kt + 1) & 1;
            const size_t koff = (size_t)(kt + 1) * 32;
#pragma unroll
            for (int p = 0; p < 4; p++) {
                int row = lrow + p * 32;
                cp_async16(sAu + (ns * GA_TILE + row * GPAD + lcol) * 4,
                           Ag + (size_t)p * 32 * K + koff);
            }
#pragma unroll
            for (int p = 0; p < 8; p++) {
                int row = lrow + p * 32;
                cp_async16(sBu + (ns * GB_TILE + row * GPAD + lcol) * 4,
                           Bg + (size_t)p * 32 * K + koff);
            }
            cp_commit();
        }

        const float* pA = sA + s * GA_TILE;
        const float* pB = sB + s * GB_TILE;

#pragma unroll
        for (int ks = 0; ks < 4; ks++) {
            const int kp = ks * 8 + 2 * cc;   // permuted (kc, kc+4) adjacent
            uint32_t af[4][4], bf[8][2];
#pragma unroll
            for (int mt = 0; mt < 4; mt++) {
                const int row = wm * 64 + mt * 16 + r0;
                float2 lo = *(const float2*)(pA + row * GPAD + kp);
                float2 hi = *(const float2*)(pA + (row + 8) * GPAD + kp);
                af[mt][0] = __float_as_uint(lo.x);
                af[mt][1] = __float_as_uint(hi.x);
                af[mt][2] = __float_as_uint(lo.y);
                af[mt][3] = __float_as_uint(hi.y);
            }
#pragma unroll
            for (int nt = 0; nt < 8; nt++) {
                const int col = wn * 64 + nt * 8 + r0;
                float2 bv = *(const float2*)(pB + col * GPAD + kp);
                bf[nt][0] = __float_as_uint(bv.x);
                bf[nt][1] = __float_as_uint(bv.y);
            }
#pragma unroll
            for (int mt = 0; mt < 4; mt++)
#pragma unroll
                for (int nt = 0; nt < 8; nt++)
                    mma_tf32(acc[mt][nt][0], acc[mt][nt][1],
                             acc[mt][nt][2], acc[mt][nt][3],
                             af[mt][0], af[mt][1], af[mt][2], af[mt][3],
                             bf[nt][0], bf[nt][1]);
        }
        // no bottom sync: next top sync orders readers before stage reuse
    }

    // epilogue: direct gmem stores with bias (C is normal layout)
#pragma unroll
    for (int mt = 0; mt < 4; mt++) {
#pragma unroll
        for (int nt = 0; nt < 8; nt++) {
            const int row = mBase + wm * 64 + mt * 16 + r0;
            const int col = nBase + wn * 64 + nt * 8 + 2 * cc;
            const float b0 = __ldg(bias + col);
            const float b1 = __ldg(bias + col + 1);
            float2 v0 = make_float2(acc[mt][nt][0] + b0, acc[mt][nt][1] + b1);
            float2 v1 = make_float2(acc[mt][nt][2] + b0, acc[mt][nt][3] + b1);
            *(float2*)(C + (size_t)row * N + col)       = v0;
            *(float2*)(C + (size_t)(row + 8) * N + col) = v1;
        }
    }
}

// ===========================================================================
// Flash attention: register-resident S/P, online softmax, m16n8k8 tf32 mma.
// EXACT R11 kernel (passing) — writes g_att in the k-permuted layout.
// ===========================================================================
#define AQ_LD 68
#define AK_LD 68
#define AV_LD 72
#define ATT_SMEM_FLOATS (128 * AQ_LD + 64 * AK_LD + 64 * AV_LD)
#define ATT_SMEM_BYTES (ATT_SMEM_FLOATS * 4)   // 70656

__global__ void __launch_bounds__(256) attn_kernel(
    const float* __restrict__ qkv, float* __restrict__ out)
{
    extern __shared__ float smf[];
    float* sQ = smf;                     // [128][AQ_LD]
    float* sK = sQ + 128 * AQ_LD;        // [64][AK_LD]
    float* sV = sK + 64 * AK_LD;         // [64][AV_LD]

    const int tid  = threadIdx.x;
    const int wid  = tid >> 5;
    const int lane = tid & 31;
    const int r0   = lane >> 2;          // 0..7
    const int cc   = lane & 3;           // 0..3

    const int itile = blockIdx.x;        // 0..3 (128 q-rows each)
    const int h     = blockIdx.y;
    const int bz    = blockIdx.z;
    const int b     = bz / CA;
    const int r     = bz % CA;
    const int qbase = h * 192;

    // ---- stage Q (scaled by 1/8, tf32-rounded) ----
    for (int idx = tid; idx < 128 * 16; idx += 256) {
        int i  = idx >> 4;
        int c4 = (idx & 15) << 2;
        size_t t = (size_t)(b * CN + itile * 128 + i) * CA + r;
        float4 v = *(const float4*)(qkv + t * CQKVN + qbase + c4);
        sQ[i * AQ_LD + c4 + 0] = tf32r(0.125f * v.x);
        sQ[i * AQ_LD + c4 + 1] = tf32r(0.125f * v.y);
        sQ[i * AQ_LD + c4 + 2] = tf32r(0.125f * v.z);
        sQ[i * AQ_LD + c4 + 3] = tf32r(0.125f * v.w);
    }

    const int arow = wid * 16 + r0;

    float m0 = -1e30f, m1 = -1e30f, l0 = 0.f, l1 = 0.f;
    float oacc[8][4];
#pragma unroll
    for (int nt = 0; nt < 8; nt++)
#pragma unroll
        for (int q = 0; q < 4; q++) oacc[nt][q] = 0.f;

    const int L1 = (lane & 28) | (cc >> 1);
    const int L2 = L1 + 2;
    const bool odd = cc & 1;

    for (int jt = 0; jt < 8; jt++) {
        __syncthreads();

        for (int idx = tid; idx < 64 * 16; idx += 256) {
            int j  = idx >> 4;
            int c4 = (idx & 15) << 2;
            size_t t = (size_t)(b * CN + jt * 64 + j) * CA + r;
            const float* base = qkv + t * CQKVN + qbase;
            float4 kv = *(const float4*)(base + 64 + c4);
            sK[j * AK_LD + c4 + 0] = tf32r(kv.x);
            sK[j * AK_LD + c4 + 1] = tf32r(kv.y);
            sK[j * AK_LD + c4 + 2] = tf32r(kv.z);
            sK[j * AK_LD + c4 + 3] = tf32r(kv.w);
            float4 vv = *(const float4*)(base + 128 + c4);
            sV[j * AV_LD + c4 + 0] = tf32r(vv.x);
            sV[j * AV_LD + c4 + 1] = tf32r(vv.y);
            sV[j * AV_LD + c4 + 2] = tf32r(vv.z);
            sV[j * AV_LD + c4 + 3] = tf32r(vv.w);
        }
        __syncthreads();

        float sacc[8][4];
#pragma unroll
        for (int nt = 0; nt < 8; nt++)
#pragma unroll
            for (int q = 0; q < 4; q++) sacc[nt][q] = 0.f;

#pragma unroll
        for (int ks = 0; ks < 8; ks++) {
            const int kc = ks * 8 + cc;
            uint32_t a0 = __float_as_uint(sQ[arow * AQ_LD + kc]);
            uint32_t a1 = __float_as_uint(sQ[(arow + 8) * AQ_LD + kc]);
            uint32_t a2 = __float_as_uint(sQ[arow * AQ_LD + kc + 4]);
            uint32_t a3 = __float_as_uint(sQ[(arow + 8) * AQ_LD + kc + 4]);
#pragma unroll
            for (int nt = 0; nt < 8; nt++) {
                const int col = nt * 8 + r0;
                uint32_t b0 = __float_as_uint(sK[col * AK_LD + kc]);
                uint32_t b1 = __float_as_uint(sK[col * AK_LD + kc + 4]);
                mma_tf32(sacc[nt][0], sacc[nt][1], sacc[nt][2], sacc[nt][3],
                         a0, a1, a2, a3, b0, b1);
            }
        }

        float mx0 = -1e30f, mx1 = -1e30f;
#pragma unroll
        for (int nt = 0; nt < 8; nt++) {
            mx0 = fmaxf(mx0, fmaxf(sacc[nt][0], sacc[nt][1]));
            mx1 = fmaxf(mx1, fmaxf(sacc[nt][2], sacc[nt][3]));
        }
        mx0 = fmaxf(mx0, __shfl_xor_sync(0xffffffffu, mx0, 1));
        mx0 = fmaxf(mx0, __shfl_xor_sync(0xffffffffu, mx0, 2));
        mx1 = fmaxf(mx1, __shfl_xor_sync(0xffffffffu, mx1, 1));
        mx1 = fmaxf(mx1, __shfl_xor_sync(0xffffffffu, mx1, 2));

        const float mn0 = fmaxf(m0, mx0);
        const float mn1 = fmaxf(m1, mx1);
        const float sc0 = __expf(m0 - mn0);
        const float sc1 = __expf(m1 - mn1);
        m0 = mn0; m1 = mn1;
        l0 *= sc0; l1 *= sc1;
#pragma unroll
        for (int nt = 0; nt < 8; nt++) {
            oacc[nt][0] *= sc0; oacc[nt][1] *= sc0;
            oacc[nt][2] *= sc1; oacc[nt][3] *= sc1;
        }
        float ps0 = 0.f, ps1 = 0.f;
#pragma unroll
        for (int nt = 0; nt < 8; nt++) {
            float p0 = tf32r(__expf(sacc[nt][0] - m0));
            float p1 = tf32r(__expf(sacc[nt][1] - m0));
            float p2 = tf32r(__expf(sacc[nt][2] - m1));
            float p3 = tf32r(__expf(sacc[nt][3] - m1));
            ps0 += p0 + p1; ps1 += p2 + p3;
            sacc[nt][0] = p0; sacc[nt][1] = p1;
            sacc[nt][2] = p2; sacc[nt][3] = p3;
        }
        l0 += ps0; l1 += ps1;

#pragma unroll
        for (int ks = 0; ks < 8; ks++) {
            float s0 = __shfl_sync(0xffffffffu, sacc[ks][0], L1);
            float s1 = __shfl_sync(0xffffffffu, sacc[ks][1], L1);
            float s2 = __shfl_sync(0xffffffffu, sacc[ks][2], L1);
            float s3 = __shfl_sync(0xffffffffu, sacc[ks][3], L1);
            float t0 = __shfl_sync(0xffffffffu, sacc[ks][0], L2);
            float t1 = __shfl_sync(0xffffffffu, sacc[ks][1], L2);
            float t2 = __shfl_sync(0xffffffffu, sacc[ks][2], L2);
            float t3 = __shfl_sync(0xffffffffu, sacc[ks][3], L2);
            uint32_t a0 = __float_as_uint(odd ? s1 : s0);
            uint32_t a1 = __float_as_uint(odd ? s3 : s2);
            uint32_t a2 = __float_as_uint(odd ? t1 : t0);
            uint32_t a3 = __float_as_uint(odd ? t3 : t2);
            const int kb = ks * 8;
#pragma unroll
            for (int nt = 0; nt < 8; nt++) {
                const int col = nt * 8 + r0;
                uint32_t b0 = __float_as_uint(sV[(kb + cc) * AV_LD + col]);
                uint32_t b1 = __float_as_uint(sV[(kb + cc + 4) * AV_LD + col]);
                mma_tf32(oacc[nt][0], oacc[nt][1], oacc[nt][2], oacc[nt][3],
                         a0, a1, a2, a3, b0, b1);
            }
        }
    }

    l0 += __shfl_xor_sync(0xffffffffu, l0, 1);
    l0 += __shfl_xor_sync(0xffffffffu, l0, 2);
    l1 += __shfl_xor_sync(0xffffffffu, l1, 1);
    l1 += __shfl_xor_sync(0xffffffffu, l1, 2);
    const float inv0 = 1.f / l0;
    const float inv1 = 1.f / l1;

    const int p0i = 2 * ((2 * cc) & 3) + ((2 * cc) >> 2);
    const int p1i = 2 * ((2 * cc + 1) & 3) + ((2 * cc + 1) >> 2);

    const size_t t0 = (size_t)(b * CN + itile * 128 + arow) * CA + r;
    const size_t t1 = (size_t)(b * CN + itile * 128 + arow + 8) * CA + r;
#pragma unroll
    for (int nt = 0; nt < 8; nt++) {
        const int base = h * 64 + nt * 8;
        out[t0 * CDIM + base + p0i] = tf32r(oacc[nt][0] * inv0);
        out[t0 * CDIM + base + p1i] = tf32r(oacc[nt][1] * inv0);
        out[t1 * CDIM + base + p0i] = tf32r(oacc[nt][2] * inv1);
        out[t1 * CDIM + base + p1i] = tf32r(oacc[nt][3] * inv1);
    }
}

// ===========================================================================
// Host side
// ===========================================================================
extern "C" void kernel_launch(void* const* d_in, const int* in_sizes, int n_in,
                              void* d_out, int out_size)
{
    const float* x      = (const float*)d_in[0];
    const float* w_qkv  = (const float*)d_in[1];
    const float* b_qkv  = (const float*)d_in[2];
    const float* w_proj = (const float*)d_in[3];
    const float* b_proj = (const float*)d_in[4];
    float* out = (float*)d_out;

    void *p0, *p1, *p2, *p3, *p4;
    cudaGetSymbolAddress(&p0, g_qkv);
    cudaGetSymbolAddress(&p1, g_att);
    cudaGetSymbolAddress(&p2, g_xr);
    cudaGetSymbolAddress(&p3, g_bt1);
    cudaGetSymbolAddress(&p4, g_bt2);
    float* qkv = (float*)p0;
    float* att = (float*)p1;
    float* xr  = (float*)p2;
    float* bt1 = (float*)p3;
    float* bt2 = (float*)p4;

    cudaFuncSetAttribute(attn_kernel,
                         cudaFuncAttributeMaxDynamicSharedMemorySize, ATT_SMEM_BYTES);
    cudaFuncSetAttribute(gemm_tf32mma,
                         cudaFuncAttributeMaxDynamicSharedMemorySize, GM_SMEM_BYTES);

    // 0) pre-passes: round+permute x, transpose+round+permute weights
    {
        int n8 = CT * CDIM / 8;
        round_perm_kernel<<<(n8 + 255) / 256, 256>>>(x, xr, n8);
        dim3 tb(32, 8);
        transpose_round_perm_kernel<<<dim3(CQKVN / 32, CDIM / 32), tb>>>(w_qkv, bt1, CDIM, CQKVN);
        transpose_round_perm_kernel<<<dim3(CDIM / 32, CDIM / 32), tb>>>(w_proj, bt2, CDIM, CDIM);
    }

    // 1) QKV projection: [T,1024] @ [1024,3072] + b
    gemm_tf32mma<<<dim3(CQKVN / 256, CT / 128), 256, GM_SMEM_BYTES>>>(
        xr, bt1, b_qkv, qkv, CQKVN, CDIM);

    // 2) flash attention (tensor-core, register-resident softmax)
    attn_kernel<<<dim3(CN / 128, CH, CB * CA), 256, ATT_SMEM_BYTES>>>(qkv, att);

    // 3) output projection: [T,1024] @ [1024,1024] + b
    gemm_tf32mma<<<dim3(CDIM / 256, CT / 128), 256, GM_SMEM_BYTES>>>(
        att, bt2, b_proj, out, CDIM, CDIM);
}

// round 13
// speedup vs baseline: 1.0156x; 1.0156x over previous
#include <cuda_runtime.h>
#include <cstdint>

// Problem constants
#define CB 2
#define CN 512
#define CA 14
#define CDIM 1024
#define CH 16
#define CD 64
#define CT (CB * CN * CA)        // 14336 tokens
#define CQKVN (3 * CDIM)         // 3072

// Scratch (device globals: allowed; no runtime allocation)
// xr, bt1, bt2, g_att use a k-permuted layout: within every 8-wide group
// along K, logical column c sits at physical 2*(c&3)+(c>>2) -> LDS.64 pairs.
__device__ float g_qkv[(size_t)CT * CQKVN];    // [T, 3072] (normal layout)
__device__ float g_att[(size_t)CT * CDIM];     // [T, 1024] k-permuted, tf32
__device__ float g_xr [(size_t)CT * CDIM];     // x, k-permuted, tf32
__device__ float g_bt1[(size_t)CQKVN * CDIM];  // w_qkv^T, k-permuted, tf32
__device__ float g_bt2[(size_t)CDIM * CDIM];   // w_proj^T, k-permuted, tf32

__device__ __forceinline__ float tf32r(float x) {
    uint32_t u;
    asm("cvt.rna.tf32.f32 %0, %1;" : "=r"(u) : "f"(x));
    return __uint_as_float(u);
}

__device__ __forceinline__ uint32_t smem_u32(const void* p) {
    uint32_t a;
    asm("{ .reg .u64 t; cvta.to.shared.u64 t, %1; cvt.u32.u64 %0, t; }"
        : "=r"(a) : "l"(p));
    return a;
}

__device__ __forceinline__ void cp_async16(uint32_t smem_addr, const void* gptr) {
    asm volatile("cp.async.ca.shared.global [%0], [%1], 16;"
                 :: "r"(smem_addr), "l"(gptr) : "memory");
}
__device__ __forceinline__ void cp_commit() {
    asm volatile("cp.async.commit_group;" ::: "memory");
}
__device__ __forceinline__ void cp_wait0() {
    asm volatile("cp.async.wait_group 0;" ::: "memory");
}

__device__ __forceinline__ void mma_tf32(
    float& c0, float& c1, float& c2, float& c3,
    uint32_t a0, uint32_t a1, uint32_t a2, uint32_t a3,
    uint32_t b0, uint32_t b1)
{
    asm volatile(
        "mma.sync.aligned.m16n8k8.row.col.f32.tf32.tf32.f32 "
        "{%0,%1,%2,%3}, {%4,%5,%6,%7}, {%8,%9}, {%0,%1,%2,%3};"
        : "+f"(c0), "+f"(c1), "+f"(c2), "+f"(c3)
        : "r"(a0), "r"(a1), "r"(a2), "r"(a3), "r"(b0), "r"(b1));
}

// ===========================================================================
// Pre-pass kernels (k-permuted outputs)
// ===========================================================================
__global__ void round_perm_kernel(const float* __restrict__ in,
                                  float* __restrict__ out, int n8)
{
    int i = blockIdx.x * blockDim.x + threadIdx.x;
    if (i < n8) {
        float4 lo = ((const float4*)in)[i * 2];
        float4 hi = ((const float4*)in)[i * 2 + 1];
        float4 p0, p1;
        p0.x = tf32r(lo.x); p0.y = tf32r(hi.x);
        p0.z = tf32r(lo.y); p0.w = tf32r(hi.y);
        p1.x = tf32r(lo.z); p1.y = tf32r(hi.z);
        p1.z = tf32r(lo.w); p1.w = tf32r(hi.w);
        ((float4*)out)[i * 2]     = p0;
        ((float4*)out)[i * 2 + 1] = p1;
    }
}

__global__ void transpose_round_perm_kernel(const float* __restrict__ in,
                                            float* __restrict__ out, int K, int N)
{
    __shared__ float t[32][33];
    int n0 = blockIdx.x * 32, k0 = blockIdx.y * 32;
    int tx = threadIdx.x;
    for (int j = threadIdx.y; j < 32; j += 8)
        t[j][tx] = in[(size_t)(k0 + j) * N + n0 + tx];
    __syncthreads();
    int px = (tx & ~7) | (2 * (tx & 3) + ((tx & 7) >> 2));
    for (int j = threadIdx.y; j < 32; j += 8)
        out[(size_t)(n0 + j) * K + k0 + px] = tf32r(t[tx][j]);
}

// ===========================================================================
// GEMM A: 128x256 CTA tile (R12 version) — used for the QKV projection.
// 1 CTA/SM, warp tile 64x64. 2-stage cp.async, k-permuted operands.
// ===========================================================================
#define GPAD 40
#define GA_TILE (128 * GPAD)
#define GB_TILE (256 * GPAD)
#define GM256_SMEM_BYTES ((2 * GA_TILE + 2 * GB_TILE) * 4)   // 122880

__global__ void __launch_bounds__(256, 1) gemm_tf32mma_256(
    const float* __restrict__ A, const float* __restrict__ Bt,
    const float* __restrict__ bias, float* __restrict__ C,
    int N, int K)
{
    extern __shared__ float sm[];
    float* sA = sm;                    // [2][128][GPAD]
    float* sB = sm + 2 * GA_TILE;      // [2][256][GPAD]

    const int tid  = threadIdx.x;
    const int wid  = tid >> 5;
    const int lane = tid & 31;
    const int wm   = wid >> 2;
    const int wn   = wid & 3;
    const int r0   = lane >> 2;
    const int cc   = lane & 3;

    const int mBase = blockIdx.y * 128;
    const int nBase = blockIdx.x * 256;

    const int lrow = tid >> 3;
    const int lcol = (tid & 7) << 2;

    const float* Ag = A  + (size_t)(mBase + lrow) * K + lcol;
    const float* Bg = Bt + (size_t)(nBase + lrow) * K + lcol;
    const uint32_t sAu = smem_u32(sA);
    const uint32_t sBu = smem_u32(sB);

    const int KIT = K >> 5;

    {
#pragma unroll
        for (int p = 0; p < 4; p++) {
            int row = lrow + p * 32;
            cp_async16(sAu + (row * GPAD + lcol) * 4, Ag + (size_t)p * 32 * K);
        }
#pragma unroll
        for (int p = 0; p < 8; p++) {
            int row = lrow + p * 32;
            cp_async16(sBu + (row * GPAD + lcol) * 4, Bg + (size_t)p * 32 * K);
        }
        cp_commit();
    }

    float acc[4][8][4];
#pragma unroll
    for (int mt = 0; mt < 4; mt++)
#pragma unroll
        for (int nt = 0; nt < 8; nt++)
#pragma unroll
            for (int q = 0; q < 4; q++) acc[mt][nt][q] = 0.f;

    for (int kt = 0; kt < KIT; kt++) {
        cp_wait0();
        __syncthreads();

        const int s = kt & 1;
        if (kt + 1 < KIT) {
            const int ns = (kt + 1) & 1;
            const size_t koff = (size_t)(kt + 1) * 32;
#pragma unroll
            for (int p = 0; p < 4; p++) {
                int row = lrow + p * 32;
                cp_async16(sAu + (ns * GA_TILE + row * GPAD + lcol) * 4,
                           Ag + (size_t)p * 32 * K + koff);
            }
#pragma unroll
            for (int p = 0; p < 8; p++) {
                int row = lrow + p * 32;
                cp_async16(sBu + (ns * GB_TILE + row * GPAD + lcol) * 4,
                           Bg + (size_t)p * 32 * K + koff);
            }
            cp_commit();
        }

        const float* pA = sA + s * GA_TILE;
        const float* pB = sB + s * GB_TILE;

#pragma unroll
        for (int ks = 0; ks < 4; ks++) {
            const int kp = ks * 8 + 2 * cc;
            uint32_t af[4][4], bf[8][2];
#pragma unroll
            for (int mt = 0; mt < 4; mt++) {
                const int row = wm * 64 + mt * 16 + r0;
                float2 lo = *(const float2*)(pA + row * GPAD + kp);
                float2 hi = *(const float2*)(pA + (row + 8) * GPAD + kp);
                af[mt][0] = __float_as_uint(lo.x);
                af[mt][1] = __float_as_uint(hi.x);
                af[mt][2] = __float_as_uint(lo.y);
                af[mt][3] = __float_as_uint(hi.y);
            }
#pragma unroll
            for (int nt = 0; nt < 8; nt++) {
                const int col = wn * 64 + nt * 8 + r0;
                float2 bv = *(const float2*)(pB + col * GPAD + kp);
                bf[nt][0] = __float_as_uint(bv.x);
                bf[nt][1] = __float_as_uint(bv.y);
            }
#pragma unroll
            for (int mt = 0; mt < 4; mt++)
#pragma unroll
                for (int nt = 0; nt < 8; nt++)
                    mma_tf32(acc[mt][nt][0], acc[mt][nt][1],
                             acc[mt][nt][2], acc[mt][nt][3],
                             af[mt][0], af[mt][1], af[mt][2], af[mt][3],
                             bf[nt][0], bf[nt][1]);
        }
    }

#pragma unroll
    for (int mt = 0; mt < 4; mt++) {
#pragma unroll
        for (int nt = 0; nt < 8; nt++) {
            const int row = mBase + wm * 64 + mt * 16 + r0;
            const int col = nBase + wn * 64 + nt * 8 + 2 * cc;
            const float b0 = __ldg(bias + col);
            const float b1 = __ldg(bias + col + 1);
            float2 v0 = make_float2(acc[mt][nt][0] + b0, acc[mt][nt][1] + b1);
            float2 v1 = make_float2(acc[mt][nt][2] + b0, acc[mt][nt][3] + b1);
            *(float2*)(C + (size_t)row * N + col)       = v0;
            *(float2*)(C + (size_t)(row + 8) * N + col) = v1;
        }
    }
}

// ===========================================================================
// GEMM B: 128x128 CTA tile (R11 version) — used for the output projection
// (better wave/tail shape at N=1024: 896 CTAs, 2 CTAs/SM, 3.03 waves).
// ===========================================================================
#define G1TILE (128 * GPAD)
#define GM128_SMEM_BYTES (2 * 2 * G1TILE * 4)   // 81920

__global__ void __launch_bounds__(256, 2) gemm_tf32mma_128(
    const float* __restrict__ A, const float* __restrict__ Bt,
    const float* __restrict__ bias, float* __restrict__ C,
    int N, int K)
{
    extern __shared__ float sm[];
    float* sA = sm;                 // [2][128][GPAD]
    float* sB = sm + 2 * G1TILE;    // [2][128][GPAD]

    const int tid  = threadIdx.x;
    const int wid  = tid >> 5;
    const int lane = tid & 31;
    const int wm   = wid >> 2;
    const int wn   = wid & 3;
    const int r0   = lane >> 2;
    const int cc   = lane & 3;

    const int mBase = blockIdx.y * 128;
    const int nBase = blockIdx.x * 128;

    const int lrow = tid >> 3;
    const int lcol = (tid & 7) << 2;

    const float* Ag = A  + (size_t)(mBase + lrow) * K + lcol;
    const float* Bg = Bt + (size_t)(nBase + lrow) * K + lcol;
    const uint32_t sAu = smem_u32(sA);
    const uint32_t sBu = smem_u32(sB);

    const int KIT = K >> 5;

    {
#pragma unroll
        for (int p = 0; p < 4; p++) {
            int row = lrow + p * 32;
            cp_async16(sAu + (row * GPAD + lcol) * 4, Ag + (size_t)p * 32 * K);
            cp_async16(sBu + (row * GPAD + lcol) * 4, Bg + (size_t)p * 32 * K);
        }
        cp_commit();
    }

    float acc[4][4][4];
#pragma unroll
    for (int mt = 0; mt < 4; mt++)
#pragma unroll
        for (int nt = 0; nt < 4; nt++)
#pragma unroll
            for (int q = 0; q < 4; q++) acc[mt][nt][q] = 0.f;

    for (int kt = 0; kt < KIT; kt++) {
        cp_wait0();
        __syncthreads();

        const int s = kt & 1;
        if (kt + 1 < KIT) {
            const int ns = (kt + 1) & 1;
            const size_t koff = (size_t)(kt + 1) * 32;
#pragma unroll
            for (int p = 0; p < 4; p++) {
                int row = lrow + p * 32;
                cp_async16(sAu + (ns * G1TILE + row * GPAD + lcol) * 4,
                           Ag + (size_t)p * 32 * K + koff);
                cp_async16(sBu + (ns * G1TILE + row * GPAD + lcol) * 4,
                           Bg + (size_t)p * 32 * K + koff);
            }
            cp_commit();
        }

        const float* pA = sA + s * G1TILE;
        const float* pB = sB + s * G1TILE;

#pragma unroll
        for (int ks = 0; ks < 4; ks++) {
            const int kp = ks * 8 + 2 * cc;
            uint32_t af[4][4], bf[4][2];
#pragma unroll
            for (int mt = 0; mt < 4; mt++) {
                const int row = wm * 64 + mt * 16 + r0;
                float2 lo = *(const float2*)(pA + row * GPAD + kp);
                float2 hi = *(const float2*)(pA + (row + 8) * GPAD + kp);
                af[mt][0] = __float_as_uint(lo.x);
                af[mt][1] = __float_as_uint(hi.x);
                af[mt][2] = __float_as_uint(lo.y);
                af[mt][3] = __float_as_uint(hi.y);
            }
#pragma unroll
            for (int nt = 0; nt < 4; nt++) {
                const int col = wn * 32 + nt * 8 + r0;
                float2 bv = *(const float2*)(pB + col * GPAD + kp);
                bf[nt][0] = __float_as_uint(bv.x);
                bf[nt][1] = __float_as_uint(bv.y);
            }
#pragma unroll
            for (int mt = 0; mt < 4; mt++)
#pragma unroll
                for (int nt = 0; nt < 4; nt++)
                    mma_tf32(acc[mt][nt][0], acc[mt][nt][1],
                             acc[mt][nt][2], acc[mt][nt][3],
                             af[mt][0], af[mt][1], af[mt][2], af[mt][3],
                             bf[nt][0], bf[nt][1]);
        }
        __syncthreads();
    }

#pragma unroll
    for (int mt = 0; mt < 4; mt++) {
#pragma unroll
        for (int nt = 0; nt < 4; nt++) {
            const int row = mBase + wm * 64 + mt * 16 + r0;
            const int col = nBase + wn * 32 + nt * 8 + 2 * cc;
            const float b0 = __ldg(bias + col);
            const float b1 = __ldg(bias + col + 1);
            float2 v0 = make_float2(acc[mt][nt][0] + b0, acc[mt][nt][1] + b1);
            float2 v1 = make_float2(acc[mt][nt][2] + b0, acc[mt][nt][3] + b1);
            *(float2*)(C + (size_t)row * N + col)       = v0;
            *(float2*)(C + (size_t)(row + 8) * N + col) = v1;
        }
    }
}

// ===========================================================================
// Flash attention: register-resident S/P, online softmax, m16n8k8 tf32 mma.
// R11 kernel + __launch_bounds__(256,2): 141KB smem for 2 CTAs/SM, overlapping
// one CTA's synchronous K/V load phase with the other's MMA phase.
// ===========================================================================
#define AQ_LD 68
#define AK_LD 68
#define AV_LD 72
#define ATT_SMEM_FLOATS (128 * AQ_LD + 64 * AK_LD + 64 * AV_LD)
#define ATT_SMEM_BYTES (ATT_SMEM_FLOATS * 4)   // 70656

__global__ void __launch_bounds__(256, 2) attn_kernel(
    const float* __restrict__ qkv, float* __restrict__ out)
{
    extern __shared__ float smf[];
    float* sQ = smf;                     // [128][AQ_LD]
    float* sK = sQ + 128 * AQ_LD;        // [64][AK_LD]
    float* sV = sK + 64 * AK_LD;         // [64][AV_LD]

    const int tid  = threadIdx.x;
    const int wid  = tid >> 5;
    const int lane = tid & 31;
    const int r0   = lane >> 2;          // 0..7
    const int cc   = lane & 3;           // 0..3

    const int itile = blockIdx.x;        // 0..3 (128 q-rows each)
    const int h     = blockIdx.y;
    const int bz    = blockIdx.z;
    const int b     = bz / CA;
    const int r     = bz % CA;
    const int qbase = h * 192;

    // ---- stage Q (scaled by 1/8, tf32-rounded) ----
    for (int idx = tid; idx < 128 * 16; idx += 256) {
        int i  = idx >> 4;
        int c4 = (idx & 15) << 2;
        size_t t = (size_t)(b * CN + itile * 128 + i) * CA + r;
        float4 v = *(const float4*)(qkv + t * CQKVN + qbase + c4);
        sQ[i * AQ_LD + c4 + 0] = tf32r(0.125f * v.x);
        sQ[i * AQ_LD + c4 + 1] = tf32r(0.125f * v.y);
        sQ[i * AQ_LD + c4 + 2] = tf32r(0.125f * v.z);
        sQ[i * AQ_LD + c4 + 3] = tf32r(0.125f * v.w);
    }

    const int arow = wid * 16 + r0;

    float m0 = -1e30f, m1 = -1e30f, l0 = 0.f, l1 = 0.f;
    float oacc[8][4];
#pragma unroll
    for (int nt = 0; nt < 8; nt++)
#pragma unroll
        for (int q = 0; q < 4; q++) oacc[nt][q] = 0.f;

    const int L1 = (lane & 28) | (cc >> 1);
    const int L2 = L1 + 2;
    const bool odd = cc & 1;

    for (int jt = 0; jt < 8; jt++) {
        __syncthreads();

        for (int idx = tid; idx < 64 * 16; idx += 256) {
            int j  = idx >> 4;
            int c4 = (idx & 15) << 2;
            size_t t = (size_t)(b * CN + jt * 64 + j) * CA + r;
            const float* base = qkv + t * CQKVN + qbase;
            float4 kv = *(const float4*)(base + 64 + c4);
            sK[j * AK_LD + c4 + 0] = tf32r(kv.x);
            sK[j * AK_LD + c4 + 1] = tf32r(kv.y);
            sK[j * AK_LD + c4 + 2] = tf32r(kv.z);
            sK[j * AK_LD + c4 + 3] = tf32r(kv.w);
            float4 vv = *(const float4*)(base + 128 + c4);
            sV[j * AV_LD + c4 + 0] = tf32r(vv.x);
            sV[j * AV_LD + c4 + 1] = tf32r(vv.y);
            sV[j * AV_LD + c4 + 2] = tf32r(vv.z);
            sV[j * AV_LD + c4 + 3] = tf32r(vv.w);
        }
        __syncthreads();

        float sacc[8][4];
#pragma unroll
        for (int nt = 0; nt < 8; nt++)
#pragma unroll
            for (int q = 0; q < 4; q++) sacc[nt][q] = 0.f;

#pragma unroll
        for (int ks = 0; ks < 8; ks++) {
            const int kc = ks * 8 + cc;
            uint32_t a0 = __float_as_uint(sQ[arow * AQ_LD + kc]);
            uint32_t a1 = __float_as_uint(sQ[(arow + 8) * AQ_LD + kc]);
            uint32_t a2 = __float_as_uint(sQ[arow * AQ_LD + kc + 4]);
            uint32_t a3 = __float_as_uint(sQ[(arow + 8) * AQ_LD + kc + 4]);
#pragma unroll
            for (int nt = 0; nt < 8; nt++) {
                const int col = nt * 8 + r0;
                uint32_t b0 = __float_as_uint(sK[col * AK_LD + kc]);
                uint32_t b1 = __float_as_uint(sK[col * AK_LD + kc + 4]);
                mma_tf32(sacc[nt][0], sacc[nt][1], sacc[nt][2], sacc[nt][3],
                         a0, a1, a2, a3, b0, b1);
            }
        }

        float mx0 = -1e30f, mx1 = -1e30f;
#pragma unroll
        for (int nt = 0; nt < 8; nt++) {
            mx0 = fmaxf(mx0, fmaxf(sacc[nt][0], sacc[nt][1]));
            mx1 = fmaxf(mx1, fmaxf(sacc[nt][2], sacc[nt][3]));
        }
        mx0 = fmaxf(mx0, __shfl_xor_sync(0xffffffffu, mx0, 1));
        mx0 = fmaxf(mx0, __shfl_xor_sync(0xffffffffu, mx0, 2));
        mx1 = fmaxf(mx1, __shfl_xor_sync(0xffffffffu, mx1, 1));
        mx1 = fmaxf(mx1, __shfl_xor_sync(0xffffffffu, mx1, 2));

        const float mn0 = fmaxf(m0, mx0);
        const float mn1 = fmaxf(m1, mx1);
        const float sc0 = __expf(m0 - mn0);
        const float sc1 = __expf(m1 - mn1);
        m0 = mn0; m1 = mn1;
        l0 *= sc0; l1 *= sc1;
#pragma unroll
        for (int nt = 0; nt < 8; nt++) {
            oacc[nt][0] *= sc0; oacc[nt][1] *= sc0;
            oacc[nt][2] *= sc1; oacc[nt][3] *= sc1;
        }
        float ps0 = 0.f, ps1 = 0.f;
#pragma unroll
        for (int nt = 0; nt < 8; nt++) {
            float p0 = tf32r(__expf(sacc[nt][0] - m0));
            float p1 = tf32r(__expf(sacc[nt][1] - m0));
            float p2 = tf32r(__expf(sacc[nt][2] - m1));
            float p3 = tf32r(__expf(sacc[nt][3] - m1));
            ps0 += p0 + p1; ps1 += p2 + p3;
            sacc[nt][0] = p0; sacc[nt][1] = p1;
            sacc[nt][2] = p2; sacc[nt][3] = p3;
        }
        l0 += ps0; l1 += ps1;

#pragma unroll
        for (int ks = 0; ks < 8; ks++) {
            float s0 = __shfl_sync(0xffffffffu, sacc[ks][0], L1);
            float s1 = __shfl_sync(0xffffffffu, sacc[ks][1], L1);
            float s2 = __shfl_sync(0xffffffffu, sacc[ks][2], L1);
            float s3 = __shfl_sync(0xffffffffu, sacc[ks][3], L1);
            float t0 = __shfl_sync(0xffffffffu, sacc[ks][0], L2);
            float t1 = __shfl_sync(0xffffffffu, sacc[ks][1], L2);
            float t2 = __shfl_sync(0xffffffffu, sacc[ks][2], L2);
            float t3 = __shfl_sync(0xffffffffu, sacc[ks][3], L2);
            uint32_t a0 = __float_as_uint(odd ? s1 : s0);
            uint32_t a1 = __float_as_uint(odd ? s3 : s2);
            uint32_t a2 = __float_as_uint(odd ? t1 : t0);
            uint32_t a3 = __float_as_uint(odd ? t3 : t2);
            const int kb = ks * 8;
#pragma unroll
            for (int nt = 0; nt < 8; nt++) {
                const int col = nt * 8 + r0;
                uint32_t b0 = __float_as_uint(sV[(kb + cc) * AV_LD + col]);
                uint32_t b1 = __float_as_uint(sV[(kb + cc + 4) * AV_LD + col]);
                mma_tf32(oacc[nt][0], oacc[nt][1], oacc[nt][2], oacc[nt][3],
                         a0, a1, a2, a3, b0, b1);
            }
        }
    }

    l0 += __shfl_xor_sync(0xffffffffu, l0, 1);
    l0 += __shfl_xor_sync(0xffffffffu, l0, 2);
    l1 += __shfl_xor_sync(0xffffffffu, l1, 1);
    l1 += __shfl_xor_sync(0xffffffffu, l1, 2);
    const float inv0 = 1.f / l0;
    const float inv1 = 1.f / l1;

    const int p0i = 2 * ((2 * cc) & 3) + ((2 * cc) >> 2);
    const int p1i = 2 * ((2 * cc + 1) & 3) + ((2 * cc + 1) >> 2);

    const size_t t0 = (size_t)(b * CN + itile * 128 + arow) * CA + r;
    const size_t t1 = (size_t)(b * CN + itile * 128 + arow + 8) * CA + r;
#pragma unroll
    for (int nt = 0; nt < 8; nt++) {
        const int base = h * 64 + nt * 8;
        out[t0 * CDIM + base + p0i] = tf32r(oacc[nt][0] * inv0);
        out[t0 * CDIM + base + p1i] = tf32r(oacc[nt][1] * inv0);
        out[t1 * CDIM + base + p0i] = tf32r(oacc[nt][2] * inv1);
        out[t1 * CDIM + base + p1i] = tf32r(oacc[nt][3] * inv1);
    }
}

// ===========================================================================
// Host side
// ===========================================================================
extern "C" void kernel_launch(void* const* d_in, const int* in_sizes, int n_in,
                              void* d_out, int out_size)
{
    const float* x      = (const float*)d_in[0];
    const float* w_qkv  = (const float*)d_in[1];
    const float* b_qkv  = (const float*)d_in[2];
    const float* w_proj = (const float*)d_in[3];
    const float* b_proj = (const float*)d_in[4];
    float* out = (float*)d_out;

    void *p0, *p1, *p2, *p3, *p4;
    cudaGetSymbolAddress(&p0, g_qkv);
    cudaGetSymbolAddress(&p1, g_att);
    cudaGetSymbolAddress(&p2, g_xr);
    cudaGetSymbolAddress(&p3, g_bt1);
    cudaGetSymbolAddress(&p4, g_bt2);
    float* qkv = (float*)p0;
    float* att = (float*)p1;
    float* xr  = (float*)p2;
    float* bt1 = (float*)p3;
    float* bt2 = (float*)p4;

    cudaFuncSetAttribute(attn_kernel,
                         cudaFuncAttributeMaxDynamicSharedMemorySize, ATT_SMEM_BYTES);
    cudaFuncSetAttribute(gemm_tf32mma_256,
                         cudaFuncAttributeMaxDynamicSharedMemorySize, GM256_SMEM_BYTES);
    cudaFuncSetAttribute(gemm_tf32mma_128,
                         cudaFuncAttributeMaxDynamicSharedMemorySize, GM128_SMEM_BYTES);

    // 0) pre-passes: round+permute x, transpose+round+permute weights
    {
        int n8 = CT * CDIM / 8;
        round_perm_kernel<<<(n8 + 255) / 256, 256>>>(x, xr, n8);
        dim3 tb(32, 8);
        transpose_round_perm_kernel<<<dim3(CQKVN / 32, CDIM / 32), tb>>>(w_qkv, bt1, CDIM, CQKVN);
        transpose_round_perm_kernel<<<dim3(CDIM / 32, CDIM / 32), tb>>>(w_proj, bt2, CDIM, CDIM);
    }

    // 1) QKV projection: [T,1024] @ [1024,3072] + b   (128x256 tile)
    gemm_tf32mma_256<<<dim3(CQKVN / 256, CT / 128), 256, GM256_SMEM_BYTES>>>(
        xr, bt1, b_qkv, qkv, CQKVN, CDIM);

    // 2) flash attention (tensor-core, register-resident softmax, 2 CTAs/SM)
    attn_kernel<<<dim3(CN / 128, CH, CB * CA), 256, ATT_SMEM_BYTES>>>(qkv, att);

    // 3) output projection: [T,1024] @ [1024,1024] + b  (128x128 tile, 2 CTAs/SM)
    gemm_tf32mma_128<<<dim3(CDIM / 128, CT / 128), 256, GM128_SMEM_BYTES>>>(
        att, bt2, b_proj, out, CDIM, CDIM);
}

// round 16
// speedup vs baseline: 1.0205x; 1.0049x over previous
#include <cuda_runtime.h>
#include <cstdint>

// Problem constants
#define CB 2
#define CN 512
#define CA 14
#define CDIM 1024
#define CH 16
#define CD 64
#define CT (CB * CN * CA)        // 14336 tokens
#define CQKVN (3 * CDIM)         // 3072

// Scratch (device globals: allowed; no runtime allocation)
// xr, bt1, bt2, g_att use a k-permuted layout: within every 8-wide group
// along K, logical column c sits at physical 2*(c&3)+(c>>2) -> LDS.64 pairs.
// g_qkv is normal layout, tf32-PRE-ROUNDED by GEMM1's epilogue.
__device__ float g_qkv[(size_t)CT * CQKVN];    // [T, 3072] tf32-rounded
__device__ float g_att[(size_t)CT * CDIM];     // [T, 1024] k-permuted, tf32
__device__ float g_xr [(size_t)CT * CDIM];     // x, k-permuted, tf32
__device__ float g_bt1[(size_t)CQKVN * CDIM];  // w_qkv^T, k-permuted, tf32
__device__ float g_bt2[(size_t)CDIM * CDIM];   // w_proj^T, k-permuted, tf32

__device__ __forceinline__ float tf32r(float x) {
    uint32_t u;
    asm("cvt.rna.tf32.f32 %0, %1;" : "=r"(u) : "f"(x));
    return __uint_as_float(u);
}

__device__ __forceinline__ uint32_t smem_u32(const void* p) {
    uint32_t a;
    asm("{ .reg .u64 t; cvta.to.shared.u64 t, %1; cvt.u32.u64 %0, t; }"
        : "=r"(a) : "l"(p));
    return a;
}

__device__ __forceinline__ void cp_async16(uint32_t smem_addr, const void* gptr) {
    asm volatile("cp.async.ca.shared.global [%0], [%1], 16;"
                 :: "r"(smem_addr), "l"(gptr) : "memory");
}
__device__ __forceinline__ void cp_commit() {
    asm volatile("cp.async.commit_group;" ::: "memory");
}
__device__ __forceinline__ void cp_wait0() {
    asm volatile("cp.async.wait_group 0;" ::: "memory");
}

__device__ __forceinline__ void mma_tf32(
    float& c0, float& c1, float& c2, float& c3,
    uint32_t a0, uint32_t a1, uint32_t a2, uint32_t a3,
    uint32_t b0, uint32_t b1)
{
    asm volatile(
        "mma.sync.aligned.m16n8k8.row.col.f32.tf32.tf32.f32 "
        "{%0,%1,%2,%3}, {%4,%5,%6,%7}, {%8,%9}, {%0,%1,%2,%3};"
        : "+f"(c0), "+f"(c1), "+f"(c2), "+f"(c3)
        : "r"(a0), "r"(a1), "r"(a2), "r"(a3), "r"(b0), "r"(b1));
}

// ===========================================================================
// Pre-pass kernels (k-permuted outputs) — unchanged from R13
// ===========================================================================
__global__ void round_perm_kernel(const float* __restrict__ in,
                                  float* __restrict__ out, int n8)
{
    int i = blockIdx.x * blockDim.x + threadIdx.x;
    if (i < n8) {
        float4 lo = ((const float4*)in)[i * 2];
        float4 hi = ((const float4*)in)[i * 2 + 1];
        float4 p0, p1;
        p0.x = tf32r(lo.x); p0.y = tf32r(hi.x);
        p0.z = tf32r(lo.y); p0.w = tf32r(hi.y);
        p1.x = tf32r(lo.z); p1.y = tf32r(hi.z);
        p1.z = tf32r(lo.w); p1.w = tf32r(hi.w);
        ((float4*)out)[i * 2]     = p0;
        ((float4*)out)[i * 2 + 1] = p1;
    }
}

__global__ void transpose_round_perm_kernel(const float* __restrict__ in,
                                            float* __restrict__ out, int K, int N)
{
    __shared__ float t[32][33];
    int n0 = blockIdx.x * 32, k0 = blockIdx.y * 32;
    int tx = threadIdx.x;
    for (int j = threadIdx.y; j < 32; j += 8)
        t[j][tx] = in[(size_t)(k0 + j) * N + n0 + tx];
    __syncthreads();
    int px = (tx & ~7) | (2 * (tx & 3) + ((tx & 7) >> 2));
    for (int j = threadIdx.y; j < 32; j += 8)
        out[(size_t)(n0 + j) * K + k0 + px] = tf32r(t[tx][j]);
}

// ===========================================================================
// GEMM A: 128x256 CTA tile — QKV projection. Epilogue tf32-ROUNDS the output
// (so attention staging is a pure bit copy). 1 CTA/SM, warp tile 64x64,
// 2-stage cp.async, k-permuted operands.
// ===========================================================================
#define GPAD 40
#define GA_TILE (128 * GPAD)
#define GB_TILE (256 * GPAD)
#define GM256_SMEM_BYTES ((2 * GA_TILE + 2 * GB_TILE) * 4)   // 122880

__global__ void __launch_bounds__(256, 1) gemm_tf32mma_256(
    const float* __restrict__ A, const float* __restrict__ Bt,
    const float* __restrict__ bias, float* __restrict__ C,
    int N, int K)
{
    extern __shared__ float sm[];
    float* sA = sm;                    // [2][128][GPAD]
    float* sB = sm + 2 * GA_TILE;      // [2][256][GPAD]

    const int tid  = threadIdx.x;
    const int wid  = tid >> 5;
    const int lane = tid & 31;
    const int wm   = wid >> 2;
    const int wn   = wid & 3;
    const int r0   = lane >> 2;
    const int cc   = lane & 3;

    const int mBase = blockIdx.y * 128;
    const int nBase = blockIdx.x * 256;

    const int lrow = tid >> 3;
    const int lcol = (tid & 7) << 2;

    const float* Ag = A  + (size_t)(mBase + lrow) * K + lcol;
    const float* Bg = Bt + (size_t)(nBase + lrow) * K + lcol;
    const uint32_t sAu = smem_u32(sA);
    const uint32_t sBu = smem_u32(sB);

    const int KIT = K >> 5;

    {
#pragma unroll
        for (int p = 0; p < 4; p++) {
            int row = lrow + p * 32;
            cp_async16(sAu + (row * GPAD + lcol) * 4, Ag + (size_t)p * 32 * K);
        }
#pragma unroll
        for (int p = 0; p < 8; p++) {
            int row = lrow + p * 32;
            cp_async16(sBu + (row * GPAD + lcol) * 4, Bg + (size_t)p * 32 * K);
        }
        cp_commit();
    }

    float acc[4][8][4];
#pragma unroll
    for (int mt = 0; mt < 4; mt++)
#pragma unroll
        for (int nt = 0; nt < 8; nt++)
#pragma unroll
            for (int q = 0; q < 4; q++) acc[mt][nt][q] = 0.f;

    for (int kt = 0; kt < KIT; kt++) {
        cp_wait0();
        __syncthreads();

        const int s = kt & 1;
        if (kt + 1 < KIT) {
            const int ns = (kt + 1) & 1;
            const size_t koff = (size_t)(kt + 1) * 32;
#pragma unroll
            for (int p = 0; p < 4; p++) {
                int row = lrow + p * 32;
                cp_async16(sAu + (ns * GA_TILE + row * GPAD + lcol) * 4,
                           Ag + (size_t)p * 32 * K + koff);
            }
#pragma unroll
            for (int p = 0; p < 8; p++) {
                int row = lrow + p * 32;
                cp_async16(sBu + (ns * GB_TILE + row * GPAD + lcol) * 4,
                           Bg + (size_t)p * 32 * K + koff);
            }
            cp_commit();
        }

        const float* pA = sA + s * GA_TILE;
        const float* pB = sB + s * GB_TILE;

#pragma unroll
        for (int ks = 0; ks < 4; ks++) {
            const int kp = ks * 8 + 2 * cc;
            uint32_t af[4][4], bf[8][2];
#pragma unroll
            for (int mt = 0; mt < 4; mt++) {
                const int row = wm * 64 + mt * 16 + r0;
                float2 lo = *(const float2*)(pA + row * GPAD + kp);
                float2 hi = *(const float2*)(pA + (row + 8) * GPAD + kp);
                af[mt][0] = __float_as_uint(lo.x);
                af[mt][1] = __float_as_uint(hi.x);
                af[mt][2] = __float_as_uint(lo.y);
                af[mt][3] = __float_as_uint(hi.y);
            }
#pragma unroll
            for (int nt = 0; nt < 8; nt++) {
                const int col = wn * 64 + nt * 8 + r0;
                float2 bv = *(const float2*)(pB + col * GPAD + kp);
                bf[nt][0] = __float_as_uint(bv.x);
                bf[nt][1] = __float_as_uint(bv.y);
            }
#pragma unroll
            for (int mt = 0; mt < 4; mt++)
#pragma unroll
                for (int nt = 0; nt < 8; nt++)
                    mma_tf32(acc[mt][nt][0], acc[mt][nt][1],
                             acc[mt][nt][2], acc[mt][nt][3],
                             af[mt][0], af[mt][1], af[mt][2], af[mt][3],
                             bf[nt][0], bf[nt][1]);
        }
    }

    // epilogue: bias + tf32 round (output feeds attention MMAs)
#pragma unroll
    for (int mt = 0; mt < 4; mt++) {
#pragma unroll
        for (int nt = 0; nt < 8; nt++) {
            const int row = mBase + wm * 64 + mt * 16 + r0;
            const int col = nBase + wn * 64 + nt * 8 + 2 * cc;
            const float b0 = __ldg(bias + col);
            const float b1 = __ldg(bias + col + 1);
            float2 v0 = make_float2(tf32r(acc[mt][nt][0] + b0),
                                    tf32r(acc[mt][nt][1] + b1));
            float2 v1 = make_float2(tf32r(acc[mt][nt][2] + b0),
                                    tf32r(acc[mt][nt][3] + b1));
            *(float2*)(C + (size_t)row * N + col)       = v0;
            *(float2*)(C + (size_t)(row + 8) * N + col) = v1;
        }
    }
}

// ===========================================================================
// GEMM B: 128x128 CTA tile — output projection. 2 CTAs/SM. (EXACT R13)
// ===========================================================================
#define G1TILE (128 * GPAD)
#define GM128_SMEM_BYTES (2 * 2 * G1TILE * 4)   // 81920

__global__ void __launch_bounds__(256, 2) gemm_tf32mma_128(
    const float* __restrict__ A, const float* __restrict__ Bt,
    const float* __restrict__ bias, float* __restrict__ C,
    int N, int K)
{
    extern __shared__ float sm[];
    float* sA = sm;                 // [2][128][GPAD]
    float* sB = sm + 2 * G1TILE;    // [2][128][GPAD]

    const int tid  = threadIdx.x;
    const int wid  = tid >> 5;
    const int lane = tid & 31;
    const int wm   = wid >> 2;
    const int wn   = wid & 3;
    const int r0   = lane >> 2;
    const int cc   = lane & 3;

    const int mBase = blockIdx.y * 128;
    const int nBase = blockIdx.x * 128;

    const int lrow = tid >> 3;
    const int lcol = (tid & 7) << 2;

    const float* Ag = A  + (size_t)(mBase + lrow) * K + lcol;
    const float* Bg = Bt + (size_t)(nBase + lrow) * K + lcol;
    const uint32_t sAu = smem_u32(sA);
    const uint32_t sBu = smem_u32(sB);

    const int KIT = K >> 5;

    {
#pragma unroll
        for (int p = 0; p < 4; p++) {
            int row = lrow + p * 32;
            cp_async16(sAu + (row * GPAD + lcol) * 4, Ag + (size_t)p * 32 * K);
            cp_async16(sBu + (row * GPAD + lcol) * 4, Bg + (size_t)p * 32 * K);
        }
        cp_commit();
    }

    float acc[4][4][4];
#pragma unroll
    for (int mt = 0; mt < 4; mt++)
#pragma unroll
        for (int nt = 0; nt < 4; nt++)
#pragma unroll
            for (int q = 0; q < 4; q++) acc[mt][nt][q] = 0.f;

    for (int kt = 0; kt < KIT; kt++) {
        cp_wait0();
        __syncthreads();

        const int s = kt & 1;
        if (kt + 1 < KIT) {
            const int ns = (kt + 1) & 1;
            const size_t koff = (size_t)(kt + 1) * 32;
#pragma unroll
            for (int p = 0; p < 4; p++) {
                int row = lrow + p * 32;
                cp_async16(sAu + (ns * G1TILE + row * GPAD + lcol) * 4,
                           Ag + (size_t)p * 32 * K + koff);
                cp_async16(sBu + (ns * G1TILE + row * GPAD + lcol) * 4,
                           Bg + (size_t)p * 32 * K + koff);
            }
            cp_commit();
        }

        const float* pA = sA + s * G1TILE;
        const float* pB = sB + s * G1TILE;

#pragma unroll
        for (int ks = 0; ks < 4; ks++) {
            const int kp = ks * 8 + 2 * cc;
            uint32_t af[4][4], bf[4][2];
#pragma unroll
            for (int mt = 0; mt < 4; mt++) {
                const int row = wm * 64 + mt * 16 + r0;
                float2 lo = *(const float2*)(pA + row * GPAD + kp);
                float2 hi = *(const float2*)(pA + (row + 8) * GPAD + kp);
                af[mt][0] = __float_as_uint(lo.x);
                af[mt][1] = __float_as_uint(hi.x);
                af[mt][2] = __float_as_uint(lo.y);
                af[mt][3] = __float_as_uint(hi.y);
            }
#pragma unroll
            for (int nt = 0; nt < 4; nt++) {
                const int col = wn * 32 + nt * 8 + r0;
                float2 bv = *(const float2*)(pB + col * GPAD + kp);
                bf[nt][0] = __float_as_uint(bv.x);
                bf[nt][1] = __float_as_uint(bv.y);
            }
#pragma unroll
            for (int mt = 0; mt < 4; mt++)
#pragma unroll
                for (int nt = 0; nt < 4; nt++)
                    mma_tf32(acc[mt][nt][0], acc[mt][nt][1],
                             acc[mt][nt][2], acc[mt][nt][3],
                             af[mt][0], af[mt][1], af[mt][2], af[mt][3],
                             bf[nt][0], bf[nt][1]);
        }
        __syncthreads();
    }

#pragma unroll
    for (int mt = 0; mt < 4; mt++) {
#pragma unroll
        for (int nt = 0; nt < 4; nt++) {
            const int row = mBase + wm * 64 + mt * 16 + r0;
            const int col = nBase + wn * 32 + nt * 8 + 2 * cc;
            const float b0 = __ldg(bias + col);
            const float b1 = __ldg(bias + col + 1);
            float2 v0 = make_float2(acc[mt][nt][0] + b0, acc[mt][nt][1] + b1);
            float2 v1 = make_float2(acc[mt][nt][2] + b0, acc[mt][nt][3] + b1);
            *(float2*)(C + (size_t)row * N + col)       = v0;
            *(float2*)(C + (size_t)(row + 8) * N + col) = v1;
        }
    }
}

// ===========================================================================
// Flash attention (R13 base, 2 CTAs/SM). ONE change vs R13: qkv arrives
// tf32-pre-rounded, so staging is vectorized LDG.128 -> STS.128 with no
// per-element cvt (Q additionally scaled by exact 0.125). S/PV phases,
// softmax, and the scatter epilogue are EXACTLY R13 (scalar LDS fragments).
// ===========================================================================
#define AQ_LD 68
#define AK_LD 68
#define AV_LD 72
#define ATT_SMEM_FLOATS (128 * AQ_LD + 64 * AK_LD + 64 * AV_LD)
#define ATT_SMEM_BYTES (ATT_SMEM_FLOATS * 4)   // 70656

__global__ void __launch_bounds__(256, 2) attn_kernel(
    const float* __restrict__ qkv, float* __restrict__ out)
{
    extern __shared__ float smf[];
    float* sQ = smf;                     // [128][AQ_LD]
    float* sK = sQ + 128 * AQ_LD;        // [64][AK_LD]
    float* sV = sK + 64 * AK_LD;         // [64][AV_LD]

    const int tid  = threadIdx.x;
    const int wid  = tid >> 5;
    const int lane = tid & 31;
    const int r0   = lane >> 2;          // 0..7
    const int cc   = lane & 3;           // 0..3

    const int itile = blockIdx.x;        // 0..3 (128 q-rows each)
    const int h     = blockIdx.y;
    const int bz    = blockIdx.z;
    const int b     = bz / CA;
    const int r     = bz % CA;
    const int qbase = h * 192;

    // ---- stage Q: LDG.128, scale by exact 1/8, STS.128 (values pre-rounded)
    for (int idx = tid; idx < 128 * 16; idx += 256) {
        int i  = idx >> 4;
        int c4 = (idx & 15) << 2;
        size_t t = (size_t)(b * CN + itile * 128 + i) * CA + r;
        float4 v = *(const float4*)(qkv + t * CQKVN + qbase + c4);
        v.x *= 0.125f; v.y *= 0.125f; v.z *= 0.125f; v.w *= 0.125f;
        *(float4*)(sQ + i * AQ_LD + c4) = v;
    }

    const int arow = wid * 16 + r0;

    float m0 = -1e30f, m1 = -1e30f, l0 = 0.f, l1 = 0.f;
    float oacc[8][4];
#pragma unroll
    for (int nt = 0; nt < 8; nt++)
#pragma unroll
        for (int q = 0; q < 4; q++) oacc[nt][q] = 0.f;

    const int L1 = (lane & 28) | (cc >> 1);
    const int L2 = L1 + 2;
    const bool odd = cc & 1;

    for (int jt = 0; jt < 8; jt++) {
        __syncthreads();

        // ---- stage K/V: pure LDG.128 -> STS.128 copies (pre-rounded) ----
        for (int idx = tid; idx < 64 * 16; idx += 256) {
            int j  = idx >> 4;
            int c4 = (idx & 15) << 2;
            size_t t = (size_t)(b * CN + jt * 64 + j) * CA + r;
            const float* base = qkv + t * CQKVN + qbase;
            *(float4*)(sK + j * AK_LD + c4) = *(const float4*)(base + 64 + c4);
            *(float4*)(sV + j * AV_LD + c4) = *(const float4*)(base + 128 + c4);
        }
        __syncthreads();

        // ---- S = Qs @ K^T (16 x 64 per warp) — scalar LDS as R13 ----
        float sacc[8][4];
#pragma unroll
        for (int nt = 0; nt < 8; nt++)
#pragma unroll
            for (int q = 0; q < 4; q++) sacc[nt][q] = 0.f;

#pragma unroll
        for (int ks = 0; ks < 8; ks++) {
            const int kc = ks * 8 + cc;
            uint32_t a0 = __float_as_uint(sQ[arow * AQ_LD + kc]);
            uint32_t a1 = __float_as_uint(sQ[(arow + 8) * AQ_LD + kc]);
            uint32_t a2 = __float_as_uint(sQ[arow * AQ_LD + kc + 4]);
            uint32_t a3 = __float_as_uint(sQ[(arow + 8) * AQ_LD + kc + 4]);
#pragma unroll
            for (int nt = 0; nt < 8; nt++) {
                const int col = nt * 8 + r0;
                uint32_t b0 = __float_as_uint(sK[col * AK_LD + kc]);
                uint32_t b1 = __float_as_uint(sK[col * AK_LD + kc + 4]);
                mma_tf32(sacc[nt][0], sacc[nt][1], sacc[nt][2], sacc[nt][3],
                         a0, a1, a2, a3, b0, b1);
            }
        }

        // ---- online softmax (rows r0 / r0+8) ----
        float mx0 = -1e30f, mx1 = -1e30f;
#pragma unroll
        for (int nt = 0; nt < 8; nt++) {
            mx0 = fmaxf(mx0, fmaxf(sacc[nt][0], sacc[nt][1]));
            mx1 = fmaxf(mx1, fmaxf(sacc[nt][2], sacc[nt][3]));
        }
        mx0 = fmaxf(mx0, __shfl_xor_sync(0xffffffffu, mx0, 1));
        mx0 = fmaxf(mx0, __shfl_xor_sync(0xffffffffu, mx0, 2));
        mx1 = fmaxf(mx1, __shfl_xor_sync(0xffffffffu, mx1, 1));
        mx1 = fmaxf(mx1, __shfl_xor_sync(0xffffffffu, mx1, 2));

        const float mn0 = fmaxf(m0, mx0);
        const float mn1 = fmaxf(m1, mx1);
        const float sc0 = __expf(m0 - mn0);
        const float sc1 = __expf(m1 - mn1);
        m0 = mn0; m1 = mn1;
        l0 *= sc0; l1 *= sc1;
#pragma unroll
        for (int nt = 0; nt < 8; nt++) {
            oacc[nt][0] *= sc0; oacc[nt][1] *= sc0;
            oacc[nt][2] *= sc1; oacc[nt][3] *= sc1;
        }
        float ps0 = 0.f, ps1 = 0.f;
#pragma unroll
        for (int nt = 0; nt < 8; nt++) {
            float p0 = tf32r(__expf(sacc[nt][0] - m0));
            float p1 = tf32r(__expf(sacc[nt][1] - m0));
            float p2 = tf32r(__expf(sacc[nt][2] - m1));
            float p3 = tf32r(__expf(sacc[nt][3] - m1));
            ps0 += p0 + p1; ps1 += p2 + p3;
            sacc[nt][0] = p0; sacc[nt][1] = p1;
            sacc[nt][2] = p2; sacc[nt][3] = p3;
        }
        l0 += ps0; l1 += ps1;

        // ---- O += P @ V (C-fragment -> A-fragment via quad shuffles) ----
#pragma unroll
        for (int ks = 0; ks < 8; ks++) {
            float s0 = __shfl_sync(0xffffffffu, sacc[ks][0], L1);
            float s1 = __shfl_sync(0xffffffffu, sacc[ks][1], L1);
            float s2 = __shfl_sync(0xffffffffu, sacc[ks][2], L1);
            float s3 = __shfl_sync(0xffffffffu, sacc[ks][3], L1);
            float t0 = __shfl_sync(0xffffffffu, sacc[ks][0], L2);
            float t1 = __shfl_sync(0xffffffffu, sacc[ks][1], L2);
            float t2 = __shfl_sync(0xffffffffu, sacc[ks][2], L2);
            float t3 = __shfl_sync(0xffffffffu, sacc[ks][3], L2);
            uint32_t a0 = __float_as_uint(odd ? s1 : s0);
            uint32_t a1 = __float_as_uint(odd ? s3 : s2);
            uint32_t a2 = __float_as_uint(odd ? t1 : t0);
            uint32_t a3 = __float_as_uint(odd ? t3 : t2);
            const int kb = ks * 8;
#pragma unroll
            for (int nt = 0; nt < 8; nt++) {
                const int col = nt * 8 + r0;
                uint32_t b0 = __float_as_uint(sV[(kb + cc) * AV_LD + col]);
                uint32_t b1 = __float_as_uint(sV[(kb + cc + 4) * AV_LD + col]);
                mma_tf32(oacc[nt][0], oacc[nt][1], oacc[nt][2], oacc[nt][3],
                         a0, a1, a2, a3, b0, b1);
            }
        }
    }

    // ---- finalize; write g_att in k-permuted layout (scatter, as R13) ----
    l0 += __shfl_xor_sync(0xffffffffu, l0, 1);
    l0 += __shfl_xor_sync(0xffffffffu, l0, 2);
    l1 += __shfl_xor_sync(0xffffffffu, l1, 1);
    l1 += __shfl_xor_sync(0xffffffffu, l1, 2);
    const float inv0 = 1.f / l0;
    const float inv1 = 1.f / l1;

    const int p0i = 2 * ((2 * cc) & 3) + ((2 * cc) >> 2);
    const int p1i = 2 * ((2 * cc + 1) & 3) + ((2 * cc + 1) >> 2);

    const size_t t0 = (size_t)(b * CN + itile * 128 + arow) * CA + r;
    const size_t t1 = (size_t)(b * CN + itile * 128 + arow + 8) * CA + r;
#pragma unroll
    for (int nt = 0; nt < 8; nt++) {
        const int base = h * 64 + nt * 8;
        out[t0 * CDIM + base + p0i] = tf32r(oacc[nt][0] * inv0);
        out[t0 * CDIM + base + p1i] = tf32r(oacc[nt][1] * inv0);
        out[t1 * CDIM + base + p0i] = tf32r(oacc[nt][2] * inv1);
        out[t1 * CDIM + base + p1i] = tf32r(oacc[nt][3] * inv1);
    }
}

// ===========================================================================
// Host side
// ===========================================================================
extern "C" void kernel_launch(void* const* d_in, const int* in_sizes, int n_in,
                              void* d_out, int out_size)
{
    const float* x      = (const float*)d_in[0];
    const float* w_qkv  = (const float*)d_in[1];
    const float* b_qkv  = (const float*)d_in[2];
    const float* w_proj = (const float*)d_in[3];
    const float* b_proj = (const float*)d_in[4];
    float* out = (float*)d_out;

    void *p0, *p1, *p2, *p3, *p4;
    cudaGetSymbolAddress(&p0, g_qkv);
    cudaGetSymbolAddress(&p1, g_att);
    cudaGetSymbolAddress(&p2, g_xr);
    cudaGetSymbolAddress(&p3, g_bt1);
    cudaGetSymbolAddress(&p4, g_bt2);
    float* qkv = (float*)p0;
    float* att = (float*)p1;
    float* xr  = (float*)p2;
    float* bt1 = (float*)p3;
    float* bt2 = (float*)p4;

    cudaFuncSetAttribute(attn_kernel,
                         cudaFuncAttributeMaxDynamicSharedMemorySize, ATT_SMEM_BYTES);
    cudaFuncSetAttribute(gemm_tf32mma_256,
                         cudaFuncAttributeMaxDynamicSharedMemorySize, GM256_SMEM_BYTES);
    cudaFuncSetAttribute(gemm_tf32mma_128,
                         cudaFuncAttributeMaxDynamicSharedMemorySize, GM128_SMEM_BYTES);

    // 0) pre-passes: round+permute x, transpose+round+permute weights
    {
        int n8 = CT * CDIM / 8;
        round_perm_kernel<<<(n8 + 255) / 256, 256>>>(x, xr, n8);
        dim3 tb(32, 8);
        transpose_round_perm_kernel<<<dim3(CQKVN / 32, CDIM / 32), tb>>>(w_qkv, bt1, CDIM, CQKVN);
        transpose_round_perm_kernel<<<dim3(CDIM / 32, CDIM / 32), tb>>>(w_proj, bt2, CDIM, CDIM);
    }

    // 1) QKV projection: [T,1024] @ [1024,3072] + b   (tf32-rounded output)
    gemm_tf32mma_256<<<dim3(CQKVN / 256, CT / 128), 256, GM256_SMEM_BYTES>>>(
        xr, bt1, b_qkv, qkv, CQKVN, CDIM);

    // 2) flash attention (tensor-core, register-resident softmax, 2 CTAs/SM)
    attn_kernel<<<dim3(CN / 128, CH, CB * CA), 256, ATT_SMEM_BYTES>>>(qkv, att);

    // 3) output projection: [T,1024] @ [1024,1024] + b  (128x128 tile, 2 CTAs/SM)
    gemm_tf32mma_128<<<dim3(CDIM / 128, CT / 128), 256, GM128_SMEM_BYTES>>>(
        att, bt2, b_proj, out, CDIM, CDIM);
}

// round 17
// speedup vs baseline: 1.0490x; 1.0279x over previous
#include <cuda_runtime.h>
#include <cstdint>

// Problem constants
#define CB 2
#define CN 512
#define CA 14
#define CDIM 1024
#define CH 16
#define CD 64
#define CT (CB * CN * CA)        // 14336 tokens
#define CQKVN (3 * CDIM)         // 3072

// Scratch (device globals: allowed; no runtime allocation)
// xr, bt1, bt2, g_att use a k-permuted layout: within every 8-wide group
// along K, logical column c sits at physical 2*(c&3)+(c>>2) -> LDS.64 pairs.
// g_qkv is normal layout, tf32-PRE-ROUNDED by GEMM1's epilogue.
__device__ float g_qkv[(size_t)CT * CQKVN];    // [T, 3072] tf32-rounded
__device__ float g_att[(size_t)CT * CDIM];     // [T, 1024] k-permuted, tf32
__device__ float g_xr [(size_t)CT * CDIM];     // x, k-permuted, tf32
__device__ float g_bt1[(size_t)CQKVN * CDIM];  // w_qkv^T, k-permuted, tf32
__device__ float g_bt2[(size_t)CDIM * CDIM];   // w_proj^T, k-permuted, tf32

__device__ __forceinline__ float tf32r(float x) {
    uint32_t u;
    asm("cvt.rna.tf32.f32 %0, %1;" : "=r"(u) : "f"(x));
    return __uint_as_float(u);
}

__device__ __forceinline__ uint32_t smem_u32(const void* p) {
    uint32_t a;
    asm("{ .reg .u64 t; cvta.to.shared.u64 t, %1; cvt.u32.u64 %0, t; }"
        : "=r"(a) : "l"(p));
    return a;
}

__device__ __forceinline__ void cp_async16(uint32_t smem_addr, const void* gptr) {
    asm volatile("cp.async.ca.shared.global [%0], [%1], 16;"
                 :: "r"(smem_addr), "l"(gptr) : "memory");
}
__device__ __forceinline__ void cp_commit() {
    asm volatile("cp.async.commit_group;" ::: "memory");
}
__device__ __forceinline__ void cp_wait0() {
    asm volatile("cp.async.wait_group 0;" ::: "memory");
}

__device__ __forceinline__ void mma_tf32(
    float& c0, float& c1, float& c2, float& c3,
    uint32_t a0, uint32_t a1, uint32_t a2, uint32_t a3,
    uint32_t b0, uint32_t b1)
{
    asm volatile(
        "mma.sync.aligned.m16n8k8.row.col.f32.tf32.tf32.f32 "
        "{%0,%1,%2,%3}, {%4,%5,%6,%7}, {%8,%9}, {%0,%1,%2,%3};"
        : "+f"(c0), "+f"(c1), "+f"(c2), "+f"(c3)
        : "r"(a0), "r"(a1), "r"(a2), "r"(a3), "r"(b0), "r"(b1));
}

// ===========================================================================
// Merged pre-pass: one launch handles x round+permute and both weight
// transposes (grid-partitioned; every block takes exactly one branch).
// ===========================================================================
#define PP_XBLOCKS (CT * CDIM / 8 / 256)                  // 7168
#define PP_W1BLOCKS ((CQKVN / 32) * (CDIM / 32))          // 3072
#define PP_W2BLOCKS ((CDIM / 32) * (CDIM / 32))           // 1024
#define PP_BLOCKS (PP_XBLOCKS + PP_W1BLOCKS + PP_W2BLOCKS)

__device__ __forceinline__ void pp_transpose(
    const float* __restrict__ in, float* __restrict__ out,
    int K, int N, int bx, int by, int tid, float (*t)[33])
{
    int n0 = bx * 32, k0 = by * 32;
    int tx = tid & 31, ty = tid >> 5;   // ty 0..7
    for (int j = ty; j < 32; j += 8)
        t[j][tx] = in[(size_t)(k0 + j) * N + n0 + tx];
    __syncthreads();
    int px = (tx & ~7) | (2 * (tx & 3) + ((tx & 7) >> 2));
    for (int j = ty; j < 32; j += 8)
        out[(size_t)(n0 + j) * K + k0 + px] = tf32r(t[tx][j]);
}

__global__ void __launch_bounds__(256) prepass_kernel(
    const float* __restrict__ x, const float* __restrict__ w_qkv,
    const float* __restrict__ w_proj,
    float* __restrict__ xr, float* __restrict__ bt1, float* __restrict__ bt2)
{
    __shared__ float t[32][33];
    const int bid = blockIdx.x;
    const int tid = threadIdx.x;

    if (bid < PP_XBLOCKS) {
        int i = bid * 256 + tid;          // exact multiple; no bound check
        float4 lo = ((const float4*)x)[i * 2];
        float4 hi = ((const float4*)x)[i * 2 + 1];
        float4 p0, p1;
        p0.x = tf32r(lo.x); p0.y = tf32r(hi.x);
        p0.z = tf32r(lo.y); p0.w = tf32r(hi.y);
        p1.x = tf32r(lo.z); p1.y = tf32r(hi.z);
        p1.z = tf32r(lo.w); p1.w = tf32r(hi.w);
        ((float4*)xr)[i * 2]     = p0;
        ((float4*)xr)[i * 2 + 1] = p1;
    } else if (bid < PP_XBLOCKS + PP_W1BLOCKS) {
        int b2 = bid - PP_XBLOCKS;
        pp_transpose(w_qkv, bt1, CDIM, CQKVN,
                     b2 % (CQKVN / 32), b2 / (CQKVN / 32), tid, t);
    } else {
        int b2 = bid - PP_XBLOCKS - PP_W1BLOCKS;
        pp_transpose(w_proj, bt2, CDIM, CDIM,
                     b2 % (CDIM / 32), b2 / (CDIM / 32), tid, t);
    }
}

// ===========================================================================
// GEMM A: 128x256 CTA tile — QKV projection, tf32-rounded output. (R16)
// ===========================================================================
#define GPAD 40
#define GA_TILE (128 * GPAD)
#define GB_TILE (256 * GPAD)
#define GM256_SMEM_BYTES ((2 * GA_TILE + 2 * GB_TILE) * 4)   // 122880

__global__ void __launch_bounds__(256, 1) gemm_tf32mma_256(
    const float* __restrict__ A, const float* __restrict__ Bt,
    const float* __restrict__ bias, float* __restrict__ C,
    int N, int K)
{
    extern __shared__ float sm[];
    float* sA = sm;                    // [2][128][GPAD]
    float* sB = sm + 2 * GA_TILE;      // [2][256][GPAD]

    const int tid  = threadIdx.x;
    const int wid  = tid >> 5;
    const int lane = tid & 31;
    const int wm   = wid >> 2;
    const int wn   = wid & 3;
    const int r0   = lane >> 2;
    const int cc   = lane & 3;

    const int mBase = blockIdx.y * 128;
    const int nBase = blockIdx.x * 256;

    const int lrow = tid >> 3;
    const int lcol = (tid & 7) << 2;

    const float* Ag = A  + (size_t)(mBase + lrow) * K + lcol;
    const float* Bg = Bt + (size_t)(nBase + lrow) * K + lcol;
    const uint32_t sAu = smem_u32(sA);
    const uint32_t sBu = smem_u32(sB);

    const int KIT = K >> 5;

    {
#pragma unroll
        for (int p = 0; p < 4; p++) {
            int row = lrow + p * 32;
            cp_async16(sAu + (row * GPAD + lcol) * 4, Ag + (size_t)p * 32 * K);
        }
#pragma unroll
        for (int p = 0; p < 8; p++) {
            int row = lrow + p * 32;
            cp_async16(sBu + (row * GPAD + lcol) * 4, Bg + (size_t)p * 32 * K);
        }
        cp_commit();
    }

    float acc[4][8][4];
#pragma unroll
    for (int mt = 0; mt < 4; mt++)
#pragma unroll
        for (int nt = 0; nt < 8; nt++)
#pragma unroll
            for (int q = 0; q < 4; q++) acc[mt][nt][q] = 0.f;

    for (int kt = 0; kt < KIT; kt++) {
        cp_wait0();
        __syncthreads();

        const int s = kt & 1;
        if (kt + 1 < KIT) {
            const int ns = (kt + 1) & 1;
            const size_t koff = (size_t)(kt + 1) * 32;
#pragma unroll
            for (int p = 0; p < 4; p++) {
                int row = lrow + p * 32;
                cp_async16(sAu + (ns * GA_TILE + row * GPAD + lcol) * 4,
                           Ag + (size_t)p * 32 * K + koff);
            }
#pragma unroll
            for (int p = 0; p < 8; p++) {
                int row = lrow + p * 32;
                cp_async16(sBu + (ns * GB_TILE + row * GPAD + lcol) * 4,
                           Bg + (size_t)p * 32 * K + koff);
            }
            cp_commit();
        }

        const float* pA = sA + s * GA_TILE;
        const float* pB = sB + s * GB_TILE;

#pragma unroll
        for (int ks = 0; ks < 4; ks++) {
            const int kp = ks * 8 + 2 * cc;
            uint32_t af[4][4], bf[8][2];
#pragma unroll
            for (int mt = 0; mt < 4; mt++) {
                const int row = wm * 64 + mt * 16 + r0;
                float2 lo = *(const float2*)(pA + row * GPAD + kp);
                float2 hi = *(const float2*)(pA + (row + 8) * GPAD + kp);
                af[mt][0] = __float_as_uint(lo.x);
                af[mt][1] = __float_as_uint(hi.x);
                af[mt][2] = __float_as_uint(lo.y);
                af[mt][3] = __float_as_uint(hi.y);
            }
#pragma unroll
            for (int nt = 0; nt < 8; nt++) {
                const int col = wn * 64 + nt * 8 + r0;
                float2 bv = *(const float2*)(pB + col * GPAD + kp);
                bf[nt][0] = __float_as_uint(bv.x);
                bf[nt][1] = __float_as_uint(bv.y);
            }
#pragma unroll
            for (int mt = 0; mt < 4; mt++)
#pragma unroll
                for (int nt = 0; nt < 8; nt++)
                    mma_tf32(acc[mt][nt][0], acc[mt][nt][1],
                             acc[mt][nt][2], acc[mt][nt][3],
                             af[mt][0], af[mt][1], af[mt][2], af[mt][3],
                             bf[nt][0], bf[nt][1]);
        }
    }

    // epilogue: bias + tf32 round (output feeds attention MMAs)
#pragma unroll
    for (int mt = 0; mt < 4; mt++) {
#pragma unroll
        for (int nt = 0; nt < 8; nt++) {
            const int row = mBase + wm * 64 + mt * 16 + r0;
            const int col = nBase + wn * 64 + nt * 8 + 2 * cc;
            const float b0 = __ldg(bias + col);
            const float b1 = __ldg(bias + col + 1);
            float2 v0 = make_float2(tf32r(acc[mt][nt][0] + b0),
                                    tf32r(acc[mt][nt][1] + b1));
            float2 v1 = make_float2(tf32r(acc[mt][nt][2] + b0),
                                    tf32r(acc[mt][nt][3] + b1));
            *(float2*)(C + (size_t)row * N + col)       = v0;
            *(float2*)(C + (size_t)(row + 8) * N + col) = v1;
        }
    }
}

// ===========================================================================
// GEMM B: 128x128 CTA tile — output projection. 2 CTAs/SM. (EXACT R13/R16)
// ===========================================================================
#define G1TILE (128 * GPAD)
#define GM128_SMEM_BYTES (2 * 2 * G1TILE * 4)   // 81920

__global__ void __launch_bounds__(256, 2) gemm_tf32mma_128(
    const float* __restrict__ A, const float* __restrict__ Bt,
    const float* __restrict__ bias, float* __restrict__ C,
    int N, int K)
{
    extern __shared__ float sm[];
    float* sA = sm;                 // [2][128][GPAD]
    float* sB = sm + 2 * G1TILE;    // [2][128][GPAD]

    const int tid  = threadIdx.x;
    const int wid  = tid >> 5;
    const int lane = tid & 31;
    const int wm   = wid >> 2;
    const int wn   = wid & 3;
    const int r0   = lane >> 2;
    const int cc   = lane & 3;

    const int mBase = blockIdx.y * 128;
    const int nBase = blockIdx.x * 128;

    const int lrow = tid >> 3;
    const int lcol = (tid & 7) << 2;

    const float* Ag = A  + (size_t)(mBase + lrow) * K + lcol;
    const float* Bg = Bt + (size_t)(nBase + lrow) * K + lcol;
    const uint32_t sAu = smem_u32(sA);
    const uint32_t sBu = smem_u32(sB);

    const int KIT = K >> 5;

    {
#pragma unroll
        for (int p = 0; p < 4; p++) {
            int row = lrow + p * 32;
            cp_async16(sAu + (row * GPAD + lcol) * 4, Ag + (size_t)p * 32 * K);
            cp_async16(sBu + (row * GPAD + lcol) * 4, Bg + (size_t)p * 32 * K);
        }
        cp_commit();
    }

    float acc[4][4][4];
#pragma unroll
    for (int mt = 0; mt < 4; mt++)
#pragma unroll
        for (int nt = 0; nt < 4; nt++)
#pragma unroll
            for (int q = 0; q < 4; q++) acc[mt][nt][q] = 0.f;

    for (int kt = 0; kt < KIT; kt++) {
        cp_wait0();
        __syncthreads();

        const int s = kt & 1;
        if (kt + 1 < KIT) {
            const int ns = (kt + 1) & 1;
            const size_t koff = (size_t)(kt + 1) * 32;
#pragma unroll
            for (int p = 0; p < 4; p++) {
                int row = lrow + p * 32;
                cp_async16(sAu + (ns * G1TILE + row * GPAD + lcol) * 4,
                           Ag + (size_t)p * 32 * K + koff);
                cp_async16(sBu + (ns * G1TILE + row * GPAD + lcol) * 4,
                           Bg + (size_t)p * 32 * K + koff);
            }
            cp_commit();
        }

        const float* pA = sA + s * G1TILE;
        const float* pB = sB + s * G1TILE;

#pragma unroll
        for (int ks = 0; ks < 4; ks++) {
            const int kp = ks * 8 + 2 * cc;
            uint32_t af[4][4], bf[4][2];
#pragma unroll
            for (int mt = 0; mt < 4; mt++) {
                const int row = wm * 64 + mt * 16 + r0;
                float2 lo = *(const float2*)(pA + row * GPAD + kp);
                float2 hi = *(const float2*)(pA + (row + 8) * GPAD + kp);
                af[mt][0] = __float_as_uint(lo.x);
                af[mt][1] = __float_as_uint(hi.x);
                af[mt][2] = __float_as_uint(lo.y);
                af[mt][3] = __float_as_uint(hi.y);
            }
#pragma unroll
            for (int nt = 0; nt < 4; nt++) {
                const int col = wn * 32 + nt * 8 + r0;
                float2 bv = *(const float2*)(pB + col * GPAD + kp);
                bf[nt][0] = __float_as_uint(bv.x);
                bf[nt][1] = __float_as_uint(bv.y);
            }
#pragma unroll
            for (int mt = 0; mt < 4; mt++)
#pragma unroll
                for (int nt = 0; nt < 4; nt++)
                    mma_tf32(acc[mt][nt][0], acc[mt][nt][1],
                             acc[mt][nt][2], acc[mt][nt][3],
                             af[mt][0], af[mt][1], af[mt][2], af[mt][3],
                             bf[nt][0], bf[nt][1]);
        }
        __syncthreads();
    }

#pragma unroll
    for (int mt = 0; mt < 4; mt++) {
#pragma unroll
        for (int nt = 0; nt < 4; nt++) {
            const int row = mBase + wm * 64 + mt * 16 + r0;
            const int col = nBase + wn * 32 + nt * 8 + 2 * cc;
            const float b0 = __ldg(bias + col);
            const float b1 = __ldg(bias + col + 1);
            float2 v0 = make_float2(acc[mt][nt][0] + b0, acc[mt][nt][1] + b1);
            float2 v1 = make_float2(acc[mt][nt][2] + b0, acc[mt][nt][3] + b1);
            *(float2*)(C + (size_t)row * N + col)       = v0;
            *(float2*)(C + (size_t)(row + 8) * N + col) = v1;
        }
    }
}

// ===========================================================================
// Flash attention (R16 base, 2 CTAs/SM). Change vs R16: 128 keys staged per
// round (double the staging MLP), computed as two 64-key sub-passes with the
// EXACT R16 compute body. Syncs per CTA: 16 -> 8. Smem 104KB/CTA (2 fit).
// ===========================================================================
#define AQ_LD 68
#define AK_LD 68
#define AV_LD 72
#define ATT_SMEM_FLOATS (128 * AQ_LD + 128 * AK_LD + 128 * AV_LD)
#define ATT_SMEM_BYTES (ATT_SMEM_FLOATS * 4)   // 106496

__global__ void __launch_bounds__(256, 2) attn_kernel(
    const float* __restrict__ qkv, float* __restrict__ out)
{
    extern __shared__ float smf[];
    float* sQ = smf;                     // [128][AQ_LD]
    float* sK = sQ + 128 * AQ_LD;        // [128][AK_LD]
    float* sV = sK + 128 * AK_LD;        // [128][AV_LD]

    const int tid  = threadIdx.x;
    const int wid  = tid >> 5;
    const int lane = tid & 31;
    const int r0   = lane >> 2;          // 0..7
    const int cc   = lane & 3;           // 0..3

    const int itile = blockIdx.x;        // 0..3 (128 q-rows each)
    const int h     = blockIdx.y;
    const int bz    = blockIdx.z;
    const int b     = bz / CA;
    const int r     = bz % CA;
    const int qbase = h * 192;

    // ---- stage Q: LDG.128, scale by exact 1/8, STS.128 (pre-rounded) ----
    for (int idx = tid; idx < 128 * 16; idx += 256) {
        int i  = idx >> 4;
        int c4 = (idx & 15) << 2;
        size_t t = (size_t)(b * CN + itile * 128 + i) * CA + r;
        float4 v = *(const float4*)(qkv + t * CQKVN + qbase + c4);
        v.x *= 0.125f; v.y *= 0.125f; v.z *= 0.125f; v.w *= 0.125f;
        *(float4*)(sQ + i * AQ_LD + c4) = v;
    }

    const int arow = wid * 16 + r0;

    float m0 = -1e30f, m1 = -1e30f, l0 = 0.f, l1 = 0.f;
    float oacc[8][4];
#pragma unroll
    for (int nt = 0; nt < 8; nt++)
#pragma unroll
        for (int q = 0; q < 4; q++) oacc[nt][q] = 0.f;

    const int L1 = (lane & 28) | (cc >> 1);
    const int L2 = L1 + 2;
    const bool odd = cc & 1;

    for (int pass = 0; pass < 4; pass++) {
        __syncthreads();

        // ---- stage 128 keys of K/V: pure LDG.128 -> STS.128 copies ----
        for (int idx = tid; idx < 128 * 16; idx += 256) {
            int j  = idx >> 4;
            int c4 = (idx & 15) << 2;
            size_t t = (size_t)(b * CN + pass * 128 + j) * CA + r;
            const float* base = qkv + t * CQKVN + qbase;
            *(float4*)(sK + j * AK_LD + c4) = *(const float4*)(base + 64 + c4);
            *(float4*)(sV + j * AV_LD + c4) = *(const float4*)(base + 128 + c4);
        }
        __syncthreads();

#pragma unroll
        for (int half = 0; half < 2; half++) {
            const float* pK = sK + half * 64 * AK_LD;
            const float* pV = sV + half * 64 * AV_LD;

            // ---- S = Qs @ K^T (16 x 64 per warp) — scalar LDS ----
            float sacc[8][4];
#pragma unroll
            for (int nt = 0; nt < 8; nt++)
#pragma unroll
                for (int q = 0; q < 4; q++) sacc[nt][q] = 0.f;

#pragma unroll
            for (int ks = 0; ks < 8; ks++) {
                const int kc = ks * 8 + cc;
                uint32_t a0 = __float_as_uint(sQ[arow * AQ_LD + kc]);
                uint32_t a1 = __float_as_uint(sQ[(arow + 8) * AQ_LD + kc]);
                uint32_t a2 = __float_as_uint(sQ[arow * AQ_LD + kc + 4]);
                uint32_t a3 = __float_as_uint(sQ[(arow + 8) * AQ_LD + kc + 4]);
#pragma unroll
                for (int nt = 0; nt < 8; nt++) {
                    const int col = nt * 8 + r0;
                    uint32_t b0 = __float_as_uint(pK[col * AK_LD + kc]);
                    uint32_t b1 = __float_as_uint(pK[col * AK_LD + kc + 4]);
                    mma_tf32(sacc[nt][0], sacc[nt][1], sacc[nt][2], sacc[nt][3],
                             a0, a1, a2, a3, b0, b1);
                }
            }

            // ---- online softmax (rows r0 / r0+8) ----
            float mx0 = -1e30f, mx1 = -1e30f;
#pragma unroll
            for (int nt = 0; nt < 8; nt++) {
                mx0 = fmaxf(mx0, fmaxf(sacc[nt][0], sacc[nt][1]));
                mx1 = fmaxf(mx1, fmaxf(sacc[nt][2], sacc[nt][3]));
            }
            mx0 = fmaxf(mx0, __shfl_xor_sync(0xffffffffu, mx0, 1));
            mx0 = fmaxf(mx0, __shfl_xor_sync(0xffffffffu, mx0, 2));
            mx1 = fmaxf(mx1, __shfl_xor_sync(0xffffffffu, mx1, 1));
            mx1 = fmaxf(mx1, __shfl_xor_sync(0xffffffffu, mx1, 2));

            const float mn0 = fmaxf(m0, mx0);
            const float mn1 = fmaxf(m1, mx1);
            const float sc0 = __expf(m0 - mn0);
            const float sc1 = __expf(m1 - mn1);
            m0 = mn0; m1 = mn1;
            l0 *= sc0; l1 *= sc1;
#pragma unroll
            for (int nt = 0; nt < 8; nt++) {
                oacc[nt][0] *= sc0; oacc[nt][1] *= sc0;
                oacc[nt][2] *= sc1; oacc[nt][3] *= sc1;
            }
            float ps0 = 0.f, ps1 = 0.f;
#pragma unroll
            for (int nt = 0; nt < 8; nt++) {
                float p0 = tf32r(__expf(sacc[nt][0] - m0));
                float p1 = tf32r(__expf(sacc[nt][1] - m0));
                float p2 = tf32r(__expf(sacc[nt][2] - m1));
                float p3 = tf32r(__expf(sacc[nt][3] - m1));
                ps0 += p0 + p1; ps1 += p2 + p3;
                sacc[nt][0] = p0; sacc[nt][1] = p1;
                sacc[nt][2] = p2; sacc[nt][3] = p3;
            }
            l0 += ps0; l1 += ps1;

            // ---- O += P @ V (C-frag -> A-frag via quad shuffles) ----
#pragma unroll
            for (int ks = 0; ks < 8; ks++) {
                float s0 = __shfl_sync(0xffffffffu, sacc[ks][0], L1);
                float s1 = __shfl_sync(0xffffffffu, sacc[ks][1], L1);
                float s2 = __shfl_sync(0xffffffffu, sacc[ks][2], L1);
                float s3 = __shfl_sync(0xffffffffu, sacc[ks][3], L1);
                float t0 = __shfl_sync(0xffffffffu, sacc[ks][0], L2);
                float t1 = __shfl_sync(0xffffffffu, sacc[ks][1], L2);
                float t2 = __shfl_sync(0xffffffffu, sacc[ks][2], L2);
                float t3 = __shfl_sync(0xffffffffu, sacc[ks][3], L2);
                uint32_t a0 = __float_as_uint(odd ? s1 : s0);
                uint32_t a1 = __float_as_uint(odd ? s3 : s2);
                uint32_t a2 = __float_as_uint(odd ? t1 : t0);
                uint32_t a3 = __float_as_uint(odd ? t3 : t2);
                const int kb = ks * 8;
#pragma unroll
                for (int nt = 0; nt < 8; nt++) {
                    const int col = nt * 8 + r0;
                    uint32_t b0 = __float_as_uint(pV[(kb + cc) * AV_LD + col]);
                    uint32_t b1 = __float_as_uint(pV[(kb + cc + 4) * AV_LD + col]);
                    mma_tf32(oacc[nt][0], oacc[nt][1], oacc[nt][2], oacc[nt][3],
                             a0, a1, a2, a3, b0, b1);
                }
            }
        }
    }

    // ---- finalize; write g_att in k-permuted layout (scatter) ----
    l0 += __shfl_xor_sync(0xffffffffu, l0, 1);
    l0 += __shfl_xor_sync(0xffffffffu, l0, 2);
    l1 += __shfl_xor_sync(0xffffffffu, l1, 1);
    l1 += __shfl_xor_sync(0xffffffffu, l1, 2);
    const float inv0 = 1.f / l0;
    const float inv1 = 1.f / l1;

    const int p0i = 2 * ((2 * cc) & 3) + ((2 * cc) >> 2);
    const int p1i = 2 * ((2 * cc + 1) & 3) + ((2 * cc + 1) >> 2);

    const size_t t0 = (size_t)(b * CN + itile * 128 + arow) * CA + r;
    const size_t t1 = (size_t)(b * CN + itile * 128 + arow + 8) * CA + r;
#pragma unroll
    for (int nt = 0; nt < 8; nt++) {
        const int base = h * 64 + nt * 8;
        out[t0 * CDIM + base + p0i] = tf32r(oacc[nt][0] * inv0);
        out[t0 * CDIM + base + p1i] = tf32r(oacc[nt][1] * inv0);
        out[t1 * CDIM + base + p0i] = tf32r(oacc[nt][2] * inv1);
        out[t1 * CDIM + base + p1i] = tf32r(oacc[nt][3] * inv1);
    }
}

// ===========================================================================
// Host side
// ===========================================================================
extern "C" void kernel_launch(void* const* d_in, const int* in_sizes, int n_in,
                              void* d_out, int out_size)
{
    const float* x      = (const float*)d_in[0];
    const float* w_qkv  = (const float*)d_in[1];
    const float* b_qkv  = (const float*)d_in[2];
    const float* w_proj = (const float*)d_in[3];
    const float* b_proj = (const float*)d_in[4];
    float* out = (float*)d_out;

    void *p0, *p1, *p2, *p3, *p4;
    cudaGetSymbolAddress(&p0, g_qkv);
    cudaGetSymbolAddress(&p1, g_att);
    cudaGetSymbolAddress(&p2, g_xr);
    cudaGetSymbolAddress(&p3, g_bt1);
    cudaGetSymbolAddress(&p4, g_bt2);
    float* qkv = (float*)p0;
    float* att = (float*)p1;
    float* xr  = (float*)p2;
    float* bt1 = (float*)p3;
    float* bt2 = (float*)p4;

    cudaFuncSetAttribute(attn_kernel,
                         cudaFuncAttributeMaxDynamicSharedMemorySize, ATT_SMEM_BYTES);
    cudaFuncSetAttribute(gemm_tf32mma_256,
                         cudaFuncAttributeMaxDynamicSharedMemorySize, GM256_SMEM_BYTES);
    cudaFuncSetAttribute(gemm_tf32mma_128,
                         cudaFuncAttributeMaxDynamicSharedMemorySize, GM128_SMEM_BYTES);

    // 0) merged pre-pass: round+permute x, transpose+round+permute weights
    prepass_kernel<<<PP_BLOCKS, 256>>>(x, w_qkv, w_proj, xr, bt1, bt2);

    // 1) QKV projection: [T,1024] @ [1024,3072] + b   (tf32-rounded output)
    gemm_tf32mma_256<<<dim3(CQKVN / 256, CT / 128), 256, GM256_SMEM_BYTES>>>(
        xr, bt1, b_qkv, qkv, CQKVN, CDIM);

    // 2) flash attention (tensor-core, register-resident softmax, 2 CTAs/SM)
    attn_kernel<<<dim3(CN / 128, CH, CB * CA), 256, ATT_SMEM_BYTES>>>(qkv, att);

    // 3) output projection: [T,1024] @ [1024,1024] + b  (128x128 tile, 2 CTAs/SM)
    gemm_tf32mma_128<<<dim3(CDIM / 128, CT / 128), 256, GM128_SMEM_BYTES>>>(
        att, bt2, b_proj, out, CDIM, CDIM);
}